// round 1
// baseline (speedup 1.0000x reference)
#include <cuda_runtime.h>
#include <math.h>

#define D_MODEL 512
#define NHEADS  8
#define TSEQ    1024
#define BATCH   4
#define M_TOTAL (BATCH * TSEQ)   /* 4096 */
#define N3      (3 * D_MODEL)    /* 1536 */

// ---------------- scratch (static __device__ allocations only) ----------------
__device__ float g_qkv[(size_t)M_TOTAL * N3];                       // 25 MB
__device__ float g_scores[(size_t)NHEADS * BATCH * TSEQ * TSEQ];    // 134 MB
__device__ float g_ctx[(size_t)M_TOTAL * D_MODEL];                  // 8 MB
__device__ float g_res[(size_t)M_TOTAL * D_MODEL];                  // 8 MB
__device__ float g_mask[NHEADS][D_MODEL];
__device__ float g_inv_scale[NHEADS];
__device__ int   g_lo[NHEADS];
__device__ int   g_hi[NHEADS];

// ---------------- prep: gate softmax, dims, masks, window bounds ----------------
__global__ void prep_kernel(const float* __restrict__ hw) {
    __shared__ float s_start[NHEADS], s_dim[NHEADS];
    int tid = threadIdx.x;
    if (tid == 0) {
        float m = hw[0];
        for (int h = 1; h < NHEADS; h++) m = fmaxf(m, hw[h]);
        float e[NHEADS]; float sum = 0.f;
        for (int h = 0; h < NHEADS; h++) { e[h] = expf(hw[h] - m); sum += e[h]; }
        float start = 0.f;
        for (int h = 0; h < NHEADS; h++) {
            float gate = e[h] / sum;
            float dim = 16.f + gate * (float)(D_MODEL - 16 * NHEADS);
            if (dim < 0.f) dim = 0.f;
            s_start[h] = start; s_dim[h] = dim;
            g_inv_scale[h] = rsqrtf(dim + 1e-6f);
            start += dim;
        }
    }
    __syncthreads();
    if (tid < D_MODEL) {
        float pos = (float)tid;
        for (int h = 0; h < NHEADS; h++) {
            float l = 1.f / (1.f + expf(-(pos - s_start[h]) * 10.f));
            float r = 1.f / (1.f + expf(-(s_start[h] + s_dim[h] - pos) * 10.f));
            g_mask[h][tid] = l * r;
        }
    }
    __syncthreads();
    if (tid == 0) {
        for (int h = 0; h < NHEADS; h++) {
            int lo = D_MODEL, hi = 0;
            for (int d = 0; d < D_MODEL; d++)
                if (g_mask[h][d] > 1e-6f) { if (d < lo) lo = d; hi = d + 1; }
            if (lo >= hi) { lo = 0; hi = 0; }
            g_lo[h] = lo; g_hi[h] = hi;
        }
    }
}

// ---------------- tiled fp32 GEMM skeleton: BM=BN=64, BK=16, 256 thr, 4x4/thr ----
#define MMA16(As, Bs, acc, tx, ty)                                        \
    _Pragma("unroll")                                                     \
    for (int k = 0; k < 16; k++) {                                        \
        float a_[4], b_[4];                                               \
        _Pragma("unroll")                                                 \
        for (int i = 0; i < 4; i++) { a_[i] = As[k][(ty)*4 + i]; b_[i] = Bs[k][(tx)*4 + i]; } \
        _Pragma("unroll")                                                 \
        for (int i = 0; i < 4; i++)                                       \
            _Pragma("unroll")                                             \
            for (int j = 0; j < 4; j++) acc[i][j] += a_[i] * b_[j];       \
    }

// ---------------- qkv = query @ Wqkv + bqkv ----------------
__global__ void qkv_gemm(const float* __restrict__ A, const float* __restrict__ W,
                         const float* __restrict__ bias) {
    __shared__ float As[16][65];
    __shared__ float Bs[16][65];
    int bm = blockIdx.y * 64, bn = blockIdx.x * 64;
    int tid = threadIdx.x, tx = tid & 15, ty = tid >> 4;
    float acc[4][4] = {};
    for (int k0 = 0; k0 < D_MODEL; k0 += 16) {
        #pragma unroll
        for (int i = tid; i < 64 * 16; i += 256) {
            int m = i >> 4, k = i & 15;
            As[k][m] = A[(size_t)(bm + m) * D_MODEL + k0 + k];
        }
        #pragma unroll
        for (int i = tid; i < 16 * 64; i += 256) {
            int k = i >> 6, n = i & 63;
            Bs[k][n] = W[(size_t)(k0 + k) * N3 + bn + n];
        }
        __syncthreads();
        MMA16(As, Bs, acc, tx, ty);
        __syncthreads();
    }
    #pragma unroll
    for (int i = 0; i < 4; i++)
        #pragma unroll
        for (int j = 0; j < 4; j++)
            g_qkv[(size_t)(bm + ty * 4 + i) * N3 + bn + tx * 4 + j] =
                acc[i][j] + bias[bn + tx * 4 + j];
}

// ---------------- scores[h,b,t,s] = (q.m_h) . (k.m_h) * inv_scale, kpm -> -1e9 ---
__global__ void scores_kernel(const unsigned char* __restrict__ kpm) {
    __shared__ float As[16][65];
    __shared__ float Bs[16][65];
    int z = blockIdx.z;                  // z = h*4 + b
    int h = z >> 2, b = z & 3;
    int t0 = blockIdx.y * 64, s0 = blockIdx.x * 64;
    int lo = g_lo[h], hi = g_hi[h];
    float invs = g_inv_scale[h];
    const float* qb = g_qkv + (size_t)b * TSEQ * N3;
    const float* kb = qb + D_MODEL;
    int tid = threadIdx.x, tx = tid & 15, ty = tid >> 4;
    float acc[4][4] = {};
    for (int k0 = lo; k0 < hi; k0 += 16) {
        #pragma unroll
        for (int i = tid; i < 1024; i += 256) {
            int m = i >> 4, k = i & 15, d = k0 + k;
            As[k][m] = (d < hi) ? qb[(size_t)(t0 + m) * N3 + d] * g_mask[h][d] : 0.f;
        }
        #pragma unroll
        for (int i = tid; i < 1024; i += 256) {
            int n = i >> 4, k = i & 15, d = k0 + k;
            Bs[k][n] = (d < hi) ? kb[(size_t)(s0 + n) * N3 + d] * g_mask[h][d] : 0.f;
        }
        __syncthreads();
        MMA16(As, Bs, acc, tx, ty);
        __syncthreads();
    }
    float* out = g_scores + ((size_t)z * TSEQ + t0) * TSEQ + s0;
    #pragma unroll
    for (int i = 0; i < 4; i++)
        #pragma unroll
        for (int j = 0; j < 4; j++) {
            int s = s0 + tx * 4 + j;
            float v = acc[i][j] * invs;
            if (kpm[b * TSEQ + s]) v = -1e9f;
            out[(size_t)(ty * 4 + i) * TSEQ + tx * 4 + j] = v;
        }
}

// ---------------- row softmax over s (1024 wide), 256 threads/row ----------------
__global__ void softmax_kernel() {
    __shared__ float shm[8];
    __shared__ float shs[8];
    size_t row = blockIdx.x;
    float* p = g_scores + row * TSEQ;
    int tid = threadIdx.x;
    float r[4];
    #pragma unroll
    for (int i = 0; i < 4; i++) r[i] = p[tid + 256 * i];
    float m = fmaxf(fmaxf(r[0], r[1]), fmaxf(r[2], r[3]));
    #pragma unroll
    for (int o = 16; o > 0; o >>= 1) m = fmaxf(m, __shfl_xor_sync(0xffffffffu, m, o));
    if ((tid & 31) == 0) shm[tid >> 5] = m;
    __syncthreads();
    m = shm[0];
    #pragma unroll
    for (int w = 1; w < 8; w++) m = fmaxf(m, shm[w]);

    float sum = 0.f;
    #pragma unroll
    for (int i = 0; i < 4; i++) { r[i] = expf(r[i] - m); sum += r[i]; }
    #pragma unroll
    for (int o = 16; o > 0; o >>= 1) sum += __shfl_xor_sync(0xffffffffu, sum, o);
    if ((tid & 31) == 0) shs[tid >> 5] = sum;
    __syncthreads();
    float total = shs[0];
    #pragma unroll
    for (int w = 1; w < 8; w++) total += shs[w];
    float inv = 1.f / total;
    #pragma unroll
    for (int i = 0; i < 4; i++) p[tid + 256 * i] = r[i] * inv;
}

// ---------------- ctx[b,t,d] = sum_h attn_h @ (v . m_h), h-loop fused ------------
__global__ void ctx_kernel() {
    __shared__ float As[16][65];
    __shared__ float Bs[16][65];
    int b = blockIdx.z;
    int t0 = blockIdx.y * 64, d0 = blockIdx.x * 64;
    int tid = threadIdx.x, tx = tid & 15, ty = tid >> 4;
    float acc[4][4] = {};
    const float* vb = g_qkv + (size_t)b * TSEQ * N3 + 2 * D_MODEL;
    for (int h = 0; h < NHEADS; h++) {
        if (g_hi[h] <= d0 || g_lo[h] >= d0 + 64) continue;
        const float* sc = g_scores + (size_t)(h * BATCH + b) * TSEQ * TSEQ;
        for (int k0 = 0; k0 < TSEQ; k0 += 16) {
            #pragma unroll
            for (int i = tid; i < 1024; i += 256) {
                int m = i >> 4, k = i & 15;
                As[k][m] = sc[(size_t)(t0 + m) * TSEQ + k0 + k];
            }
            #pragma unroll
            for (int i = tid; i < 1024; i += 256) {
                int k = i >> 6, n = i & 63;
                Bs[k][n] = vb[(size_t)(k0 + k) * N3 + d0 + n] * g_mask[h][d0 + n];
            }
            __syncthreads();
            MMA16(As, Bs, acc, tx, ty);
            __syncthreads();
        }
    }
    #pragma unroll
    for (int i = 0; i < 4; i++)
        #pragma unroll
        for (int j = 0; j < 4; j++)
            g_ctx[(size_t)(b * TSEQ + t0 + ty * 4 + i) * D_MODEL + d0 + tx * 4 + j] = acc[i][j];
}

// ---------------- res = ctx @ Wout + bout + query ----------------
__global__ void out_gemm(const float* __restrict__ W, const float* __restrict__ bias,
                         const float* __restrict__ query) {
    __shared__ float As[16][65];
    __shared__ float Bs[16][65];
    int bm = blockIdx.y * 64, bn = blockIdx.x * 64;
    int tid = threadIdx.x, tx = tid & 15, ty = tid >> 4;
    float acc[4][4] = {};
    for (int k0 = 0; k0 < D_MODEL; k0 += 16) {
        #pragma unroll
        for (int i = tid; i < 64 * 16; i += 256) {
            int m = i >> 4, k = i & 15;
            As[k][m] = g_ctx[(size_t)(bm + m) * D_MODEL + k0 + k];
        }
        #pragma unroll
        for (int i = tid; i < 16 * 64; i += 256) {
            int k = i >> 6, n = i & 63;
            Bs[k][n] = W[(size_t)(k0 + k) * D_MODEL + bn + n];
        }
        __syncthreads();
        MMA16(As, Bs, acc, tx, ty);
        __syncthreads();
    }
    #pragma unroll
    for (int i = 0; i < 4; i++)
        #pragma unroll
        for (int j = 0; j < 4; j++) {
            size_t idx = (size_t)(bm + ty * 4 + i) * D_MODEL + bn + tx * 4 + j;
            g_res[idx] = acc[i][j] + bias[bn + tx * 4 + j] + query[idx];
        }
}

// ---------------- layernorm per row ----------------
__global__ void ln_kernel(const float* __restrict__ gamma, const float* __restrict__ beta,
                          float* __restrict__ out) {
    __shared__ float shs[8];
    __shared__ float shq[8];
    int row = blockIdx.x;
    const float* x = g_res + (size_t)row * D_MODEL;
    int tid = threadIdx.x;
    float v0 = x[tid], v1 = x[tid + 256];
    float s = v0 + v1, sq = v0 * v0 + v1 * v1;
    #pragma unroll
    for (int o = 16; o > 0; o >>= 1) {
        s  += __shfl_xor_sync(0xffffffffu, s, o);
        sq += __shfl_xor_sync(0xffffffffu, sq, o);
    }
    if ((tid & 31) == 0) { shs[tid >> 5] = s; shq[tid >> 5] = sq; }
    __syncthreads();
    s = 0.f; sq = 0.f;
    #pragma unroll
    for (int w = 0; w < 8; w++) { s += shs[w]; sq += shq[w]; }
    float mu = s * (1.f / D_MODEL);
    float var = sq * (1.f / D_MODEL) - mu * mu;
    float inv = rsqrtf(var + 1e-5f);
    out[(size_t)row * D_MODEL + tid]       = (v0 - mu) * inv * gamma[tid] + beta[tid];
    out[(size_t)row * D_MODEL + tid + 256] = (v1 - mu) * inv * gamma[tid + 256] + beta[tid + 256];
}

// ---------------- launch ----------------
extern "C" void kernel_launch(void* const* d_in, const int* in_sizes, int n_in,
                              void* d_out, int out_size) {
    const float*         query = (const float*)d_in[0];
    const float*         hw    = (const float*)d_in[1];
    const float*         Wqkv  = (const float*)d_in[2];
    const float*         bqkv  = (const float*)d_in[3];
    const float*         Wout  = (const float*)d_in[4];
    const float*         bout  = (const float*)d_in[5];
    const float*         gamma = (const float*)d_in[6];
    const float*         beta  = (const float*)d_in[7];
    const unsigned char* kpm   = (const unsigned char*)d_in[8];
    float* out = (float*)d_out;

    prep_kernel<<<1, 512>>>(hw);
    qkv_gemm<<<dim3(N3 / 64, M_TOTAL / 64), 256>>>(query, Wqkv, bqkv);
    scores_kernel<<<dim3(TSEQ / 64, TSEQ / 64, NHEADS * BATCH), 256>>>(kpm);
    softmax_kernel<<<NHEADS * BATCH * TSEQ, 256>>>();
    ctx_kernel<<<dim3(D_MODEL / 64, TSEQ / 64, BATCH), 256>>>();
    out_gemm<<<dim3(D_MODEL / 64, M_TOTAL / 64), 256>>>(Wout, bout, query);
    ln_kernel<<<M_TOTAL, 256>>>(gamma, beta, out);
}

// round 2
// speedup vs baseline: 2.5902x; 2.5902x over previous
#include <cuda_runtime.h>
#include <math.h>
#include <stdint.h>

#define D_MODEL 512
#define NHEADS  8
#define TSEQ    1024
#define BATCH   4
#define M_TOTAL (BATCH * TSEQ)   /* 4096 */
#define N3      (3 * D_MODEL)    /* 1536 */

#define PAD_MK 76   /* [mn][k] tiles: 64 rows x 32 k, pad 76 (16B aligned, conflict-free frags) */
#define PAD_KN 68   /* [k][n] tiles: 32 rows x 64 n, pad 68 */

// ---------------- scratch ----------------
__device__ float g_qkv[(size_t)M_TOTAL * N3];
__device__ float g_scores[(size_t)NHEADS * BATCH * TSEQ * TSEQ];
__device__ float g_ctx[(size_t)M_TOTAL * D_MODEL];
__device__ float g_res[(size_t)M_TOTAL * D_MODEL];
__device__ float g_mask[NHEADS][D_MODEL];
__device__ float g_inv_scale[NHEADS];
__device__ int   g_lo[NHEADS];
__device__ int   g_hi[NHEADS];

// ---------------- helpers ----------------
__device__ __forceinline__ unsigned f2tf32(float x) {
    unsigned u; asm("cvt.rna.tf32.f32 %0, %1;\n" : "=r"(u) : "f"(x)); return u;
}

__device__ __forceinline__ void mma_tf32(float d[4], const unsigned a[4], const unsigned b[2]) {
    asm volatile(
        "mma.sync.aligned.m16n8k8.row.col.f32.tf32.tf32.f32 "
        "{%0,%1,%2,%3}, {%4,%5,%6,%7}, {%8,%9}, {%0,%1,%2,%3};\n"
        : "+f"(d[0]), "+f"(d[1]), "+f"(d[2]), "+f"(d[3])
        : "r"(a[0]), "r"(a[1]), "r"(a[2]), "r"(a[3]), "r"(b[0]), "r"(b[1]));
}

// Load 64 rows x 32 k tile into [row][k] (pad PAD_MK), optional mask over k.
// gmem: row-major, k contiguous. 128 threads.
__device__ __forceinline__ void load_mk(unsigned* T, const float* __restrict__ g, size_t ld,
                                        int k0, int tid, const float* __restrict__ mask) {
    #pragma unroll
    for (int it = 0; it < 4; it++) {
        int i = tid + it * 128;
        int r = i >> 3, q = (i & 7) * 4;
        float4 v = *(const float4*)(g + (size_t)r * ld + k0 + q);
        if (mask) {
            v.x *= mask[k0 + q];     v.y *= mask[k0 + q + 1];
            v.z *= mask[k0 + q + 2]; v.w *= mask[k0 + q + 3];
        }
        uint4 u = make_uint4(f2tf32(v.x), f2tf32(v.y), f2tf32(v.z), f2tf32(v.w));
        *(uint4*)(T + r * PAD_MK + q) = u;
    }
}

// Load 32 k x 64 n tile into [k][n] (pad PAD_KN), optional mask over n (local idx).
// gmem: k-major rows, n contiguous. g points at (k=0 global row base, n tile base).
__device__ __forceinline__ void load_kn(unsigned* T, const float* __restrict__ g, size_t ld,
                                        int k0, int tid, const float* __restrict__ maskn) {
    #pragma unroll
    for (int it = 0; it < 4; it++) {
        int i = tid + it * 128;
        int k = i >> 4, q = (i & 15) * 4;
        float4 v = *(const float4*)(g + (size_t)(k0 + k) * ld + q);
        if (maskn) {
            v.x *= maskn[q];     v.y *= maskn[q + 1];
            v.z *= maskn[q + 2]; v.w *= maskn[q + 3];
        }
        uint4 u = make_uint4(f2tf32(v.x), f2tf32(v.y), f2tf32(v.z), f2tf32(v.w));
        *(uint4*)(T + k * PAD_KN + q) = u;
    }
}

// One BK=32 tile of MMA. BLAY: 0 = B in [n][k] (PAD_MK), 1 = B in [k][n] (PAD_KN).
template <int BLAY>
__device__ __forceinline__ void mma_tile(float c[2][4][4], const unsigned* As, const unsigned* Bs,
                                         int wm, int wn, int g, int tig) {
    #pragma unroll
    for (int kq = 0; kq < 32; kq += 8) {
        unsigned a[2][4], b[4][2];
        #pragma unroll
        for (int mt = 0; mt < 2; mt++) {
            int mr = wm * 32 + mt * 16;
            a[mt][0] = As[(mr + g) * PAD_MK + kq + tig];
            a[mt][1] = As[(mr + g + 8) * PAD_MK + kq + tig];
            a[mt][2] = As[(mr + g) * PAD_MK + kq + tig + 4];
            a[mt][3] = As[(mr + g + 8) * PAD_MK + kq + tig + 4];
        }
        #pragma unroll
        for (int nt = 0; nt < 4; nt++) {
            int nr = wn * 32 + nt * 8;
            if (BLAY == 0) {
                b[nt][0] = Bs[(nr + g) * PAD_MK + kq + tig];
                b[nt][1] = Bs[(nr + g) * PAD_MK + kq + tig + 4];
            } else {
                b[nt][0] = Bs[(kq + tig) * PAD_KN + nr + g];
                b[nt][1] = Bs[(kq + tig + 4) * PAD_KN + nr + g];
            }
        }
        #pragma unroll
        for (int mt = 0; mt < 2; mt++)
            #pragma unroll
            for (int nt = 0; nt < 4; nt++)
                mma_tf32(c[mt][nt], a[mt], b[nt]);
    }
}

// ---------------- prep ----------------
__global__ void prep_kernel(const float* __restrict__ hw) {
    __shared__ float s_start[NHEADS], s_dim[NHEADS];
    int tid = threadIdx.x;
    if (tid == 0) {
        float m = hw[0];
        for (int h = 1; h < NHEADS; h++) m = fmaxf(m, hw[h]);
        float e[NHEADS]; float sum = 0.f;
        for (int h = 0; h < NHEADS; h++) { e[h] = expf(hw[h] - m); sum += e[h]; }
        float start = 0.f;
        for (int h = 0; h < NHEADS; h++) {
            float gate = e[h] / sum;
            float dim = 16.f + gate * (float)(D_MODEL - 16 * NHEADS);
            if (dim < 0.f) dim = 0.f;
            s_start[h] = start; s_dim[h] = dim;
            g_inv_scale[h] = rsqrtf(dim + 1e-6f);
            start += dim;
        }
    }
    __syncthreads();
    if (tid < D_MODEL) {
        float pos = (float)tid;
        for (int h = 0; h < NHEADS; h++) {
            float l = 1.f / (1.f + expf(-(pos - s_start[h]) * 10.f));
            float r = 1.f / (1.f + expf(-(s_start[h] + s_dim[h] - pos) * 10.f));
            g_mask[h][tid] = l * r;
        }
    }
    __syncthreads();
    if (tid == 0) {
        for (int h = 0; h < NHEADS; h++) {
            int lo = D_MODEL, hi = 0;
            for (int d = 0; d < D_MODEL; d++)
                if (g_mask[h][d] > 1e-6f) { if (d < lo) lo = d; hi = d + 1; }
            if (lo >= hi) { lo = 0; hi = 0; }
            g_lo[h] = lo; g_hi[h] = hi;
        }
    }
}

// ---------------- qkv = query @ Wqkv + bqkv ----------------
__global__ __launch_bounds__(128) void qkv_gemm(const float* __restrict__ A,
                                                const float* __restrict__ W,
                                                const float* __restrict__ bias) {
    __shared__ unsigned As[64 * PAD_MK];
    __shared__ unsigned Bs[32 * PAD_KN];
    int bm = blockIdx.y * 64, bn = blockIdx.x * 64;
    int tid = threadIdx.x, w = tid >> 5, lane = tid & 31;
    int wm = w >> 1, wn = w & 1, g = lane >> 2, tig = lane & 3;
    float c[2][4][4] = {};
    for (int k0 = 0; k0 < D_MODEL; k0 += 32) {
        load_mk(As, A + (size_t)bm * D_MODEL, D_MODEL, k0, tid, nullptr);
        load_kn(Bs, W + bn, N3, k0, tid, nullptr);
        __syncthreads();
        mma_tile<1>(c, As, Bs, wm, wn, g, tig);
        __syncthreads();
    }
    #pragma unroll
    for (int mt = 0; mt < 2; mt++)
        #pragma unroll
        for (int nt = 0; nt < 4; nt++) {
            int row = bm + wm * 32 + mt * 16 + g;
            int col = bn + wn * 32 + nt * 8 + tig * 2;
            g_qkv[(size_t)row * N3 + col]           = c[mt][nt][0] + bias[col];
            g_qkv[(size_t)row * N3 + col + 1]       = c[mt][nt][1] + bias[col + 1];
            g_qkv[(size_t)(row + 8) * N3 + col]     = c[mt][nt][2] + bias[col];
            g_qkv[(size_t)(row + 8) * N3 + col + 1] = c[mt][nt][3] + bias[col + 1];
        }
}

// ---------------- scores ----------------
__global__ __launch_bounds__(128) void scores_kernel(const unsigned char* __restrict__ kpm) {
    __shared__ unsigned As[64 * PAD_MK];
    __shared__ unsigned Bs[64 * PAD_MK];
    int z = blockIdx.z, h = z >> 2, b = z & 3;
    int t0 = blockIdx.y * 64, s0 = blockIdx.x * 64;
    int klo = g_lo[h] & ~31;
    int khi = g_hi[h] + 31; khi &= ~31; if (khi > D_MODEL) khi = D_MODEL;
    float invs = g_inv_scale[h];
    const float* qb = g_qkv + (size_t)b * TSEQ * N3;
    const float* kb = qb + D_MODEL;
    const float* mask = g_mask[h];
    int tid = threadIdx.x, w = tid >> 5, lane = tid & 31;
    int wm = w >> 1, wn = w & 1, g = lane >> 2, tig = lane & 3;
    float c[2][4][4] = {};
    for (int k0 = klo; k0 < khi; k0 += 32) {
        load_mk(As, qb + (size_t)t0 * N3, N3, k0, tid, mask);
        load_mk(Bs, kb + (size_t)s0 * N3, N3, k0, tid, mask);
        __syncthreads();
        mma_tile<0>(c, As, Bs, wm, wn, g, tig);
        __syncthreads();
    }
    float* out = g_scores + ((size_t)z * TSEQ + t0) * TSEQ + s0;
    const unsigned char* kp = kpm + b * TSEQ;
    #pragma unroll
    for (int mt = 0; mt < 2; mt++)
        #pragma unroll
        for (int nt = 0; nt < 4; nt++) {
            int row = wm * 32 + mt * 16 + g;
            int col = wn * 32 + nt * 8 + tig * 2;
            float v0 = c[mt][nt][0] * invs, v1 = c[mt][nt][1] * invs;
            float v2 = c[mt][nt][2] * invs, v3 = c[mt][nt][3] * invs;
            if (kp[s0 + col])     { v0 = -1e9f; v2 = -1e9f; }
            if (kp[s0 + col + 1]) { v1 = -1e9f; v3 = -1e9f; }
            out[(size_t)row * TSEQ + col]           = v0;
            out[(size_t)row * TSEQ + col + 1]       = v1;
            out[(size_t)(row + 8) * TSEQ + col]     = v2;
            out[(size_t)(row + 8) * TSEQ + col + 1] = v3;
        }
}

// ---------------- row softmax ----------------
__global__ void softmax_kernel() {
    __shared__ float shm[8];
    __shared__ float shs[8];
    size_t row = blockIdx.x;
    float* p = g_scores + row * TSEQ;
    int tid = threadIdx.x;
    float r[4];
    #pragma unroll
    for (int i = 0; i < 4; i++) r[i] = p[tid + 256 * i];
    float m = fmaxf(fmaxf(r[0], r[1]), fmaxf(r[2], r[3]));
    #pragma unroll
    for (int o = 16; o > 0; o >>= 1) m = fmaxf(m, __shfl_xor_sync(0xffffffffu, m, o));
    if ((tid & 31) == 0) shm[tid >> 5] = m;
    __syncthreads();
    m = shm[0];
    #pragma unroll
    for (int w = 1; w < 8; w++) m = fmaxf(m, shm[w]);
    float sum = 0.f;
    #pragma unroll
    for (int i = 0; i < 4; i++) { r[i] = expf(r[i] - m); sum += r[i]; }
    #pragma unroll
    for (int o = 16; o > 0; o >>= 1) sum += __shfl_xor_sync(0xffffffffu, sum, o);
    if ((tid & 31) == 0) shs[tid >> 5] = sum;
    __syncthreads();
    float total = shs[0];
    #pragma unroll
    for (int w = 1; w < 8; w++) total += shs[w];
    float inv = 1.f / total;
    #pragma unroll
    for (int i = 0; i < 4; i++) p[tid + 256 * i] = r[i] * inv;
}

// ---------------- ctx = sum_h attn_h @ (v . m_h) ----------------
__global__ __launch_bounds__(128) void ctx_kernel() {
    __shared__ unsigned As[64 * PAD_MK];
    __shared__ unsigned Bs[32 * PAD_KN];
    int b = blockIdx.z;
    int t0 = blockIdx.y * 64, d0 = blockIdx.x * 64;
    int tid = threadIdx.x, w = tid >> 5, lane = tid & 31;
    int wm = w >> 1, wn = w & 1, g = lane >> 2, tig = lane & 3;
    float c[2][4][4] = {};
    const float* vb = g_qkv + (size_t)b * TSEQ * N3 + 2 * D_MODEL;
    for (int h = 0; h < NHEADS; h++) {
        if (g_hi[h] <= d0 || g_lo[h] >= d0 + 64) continue;
        const float* sc = g_scores + (size_t)(h * BATCH + b) * TSEQ * TSEQ;
        const float* maskn = g_mask[h] + d0;
        for (int k0 = 0; k0 < TSEQ; k0 += 32) {
            load_mk(As, sc + (size_t)t0 * TSEQ, TSEQ, k0, tid, nullptr);
            load_kn(Bs, vb + d0, N3, k0, tid, maskn);
            __syncthreads();
            mma_tile<1>(c, As, Bs, wm, wn, g, tig);
            __syncthreads();
        }
    }
    #pragma unroll
    for (int mt = 0; mt < 2; mt++)
        #pragma unroll
        for (int nt = 0; nt < 4; nt++) {
            int row = b * TSEQ + t0 + wm * 32 + mt * 16 + g;
            int col = d0 + wn * 32 + nt * 8 + tig * 2;
            g_ctx[(size_t)row * D_MODEL + col]           = c[mt][nt][0];
            g_ctx[(size_t)row * D_MODEL + col + 1]       = c[mt][nt][1];
            g_ctx[(size_t)(row + 8) * D_MODEL + col]     = c[mt][nt][2];
            g_ctx[(size_t)(row + 8) * D_MODEL + col + 1] = c[mt][nt][3];
        }
}

// ---------------- res = ctx @ Wout + bout + query ----------------
__global__ __launch_bounds__(128) void out_gemm(const float* __restrict__ W,
                                                const float* __restrict__ bias,
                                                const float* __restrict__ query) {
    __shared__ unsigned As[64 * PAD_MK];
    __shared__ unsigned Bs[32 * PAD_KN];
    int bm = blockIdx.y * 64, bn = blockIdx.x * 64;
    int tid = threadIdx.x, w = tid >> 5, lane = tid & 31;
    int wm = w >> 1, wn = w & 1, g = lane >> 2, tig = lane & 3;
    float c[2][4][4] = {};
    for (int k0 = 0; k0 < D_MODEL; k0 += 32) {
        load_mk(As, g_ctx + (size_t)bm * D_MODEL, D_MODEL, k0, tid, nullptr);
        load_kn(Bs, W + bn, D_MODEL, k0, tid, nullptr);
        __syncthreads();
        mma_tile<1>(c, As, Bs, wm, wn, g, tig);
        __syncthreads();
    }
    #pragma unroll
    for (int mt = 0; mt < 2; mt++)
        #pragma unroll
        for (int nt = 0; nt < 4; nt++) {
            int row = bm + wm * 32 + mt * 16 + g;
            int col = bn + wn * 32 + nt * 8 + tig * 2;
            size_t i0 = (size_t)row * D_MODEL + col;
            size_t i2 = (size_t)(row + 8) * D_MODEL + col;
            g_res[i0]     = c[mt][nt][0] + bias[col]     + query[i0];
            g_res[i0 + 1] = c[mt][nt][1] + bias[col + 1] + query[i0 + 1];
            g_res[i2]     = c[mt][nt][2] + bias[col]     + query[i2];
            g_res[i2 + 1] = c[mt][nt][3] + bias[col + 1] + query[i2 + 1];
        }
}

// ---------------- layernorm ----------------
__global__ void ln_kernel(const float* __restrict__ gamma, const float* __restrict__ beta,
                          float* __restrict__ out) {
    __shared__ float shs[8];
    __shared__ float shq[8];
    int row = blockIdx.x;
    const float* x = g_res + (size_t)row * D_MODEL;
    int tid = threadIdx.x;
    float v0 = x[tid], v1 = x[tid + 256];
    float s = v0 + v1, sq = v0 * v0 + v1 * v1;
    #pragma unroll
    for (int o = 16; o > 0; o >>= 1) {
        s  += __shfl_xor_sync(0xffffffffu, s, o);
        sq += __shfl_xor_sync(0xffffffffu, sq, o);
    }
    if ((tid & 31) == 0) { shs[tid >> 5] = s; shq[tid >> 5] = sq; }
    __syncthreads();
    s = 0.f; sq = 0.f;
    #pragma unroll
    for (int w = 0; w < 8; w++) { s += shs[w]; sq += shq[w]; }
    float mu = s * (1.f / D_MODEL);
    float var = sq * (1.f / D_MODEL) - mu * mu;
    float inv = rsqrtf(var + 1e-5f);
    out[(size_t)row * D_MODEL + tid]       = (v0 - mu) * inv * gamma[tid] + beta[tid];
    out[(size_t)row * D_MODEL + tid + 256] = (v1 - mu) * inv * gamma[tid + 256] + beta[tid + 256];
}

// ---------------- launch ----------------
extern "C" void kernel_launch(void* const* d_in, const int* in_sizes, int n_in,
                              void* d_out, int out_size) {
    const float*         query = (const float*)d_in[0];
    const float*         hw    = (const float*)d_in[1];
    const float*         Wqkv  = (const float*)d_in[2];
    const float*         bqkv  = (const float*)d_in[3];
    const float*         Wout  = (const float*)d_in[4];
    const float*         bout  = (const float*)d_in[5];
    const float*         gamma = (const float*)d_in[6];
    const float*         beta  = (const float*)d_in[7];
    const unsigned char* kpm   = (const unsigned char*)d_in[8];
    float* out = (float*)d_out;

    prep_kernel<<<1, 512>>>(hw);
    qkv_gemm<<<dim3(N3 / 64, M_TOTAL / 64), 128>>>(query, Wqkv, bqkv);
    scores_kernel<<<dim3(TSEQ / 64, TSEQ / 64, NHEADS * BATCH), 128>>>(kpm);
    softmax_kernel<<<NHEADS * BATCH * TSEQ, 256>>>();
    ctx_kernel<<<dim3(D_MODEL / 64, TSEQ / 64, BATCH), 128>>>();
    out_gemm<<<dim3(D_MODEL / 64, M_TOTAL / 64), 128>>>(Wout, bout, query);
    ln_kernel<<<M_TOTAL, 256>>>(gamma, beta, out);
}

// round 3
// speedup vs baseline: 3.0623x; 1.1823x over previous
#include <cuda_runtime.h>
#include <math.h>
#include <stdint.h>

#define D_MODEL 512
#define NHEADS  8
#define TSEQ    1024
#define BATCH   4
#define M_TOTAL (BATCH * TSEQ)   /* 4096 */
#define N3      (3 * D_MODEL)    /* 1536 */

#define PITCH_MK 36   /* [mn][k] tiles: rows x 32k, pitch 36 -> bank 4g+tig, conflict-free */
#define PITCH_KN 72   /* [k][n] tiles: 32k x 64n, pitch 72 -> bank 8tig+g, conflict-free */

// ---------------- scratch ----------------
__device__ float g_qkv[(size_t)M_TOTAL * N3];
__device__ float g_ctx[(size_t)M_TOTAL * D_MODEL];
__device__ float g_res[(size_t)M_TOTAL * D_MODEL];
__device__ float g_mask[NHEADS][D_MODEL];
__device__ float g_inv_scale[NHEADS];
__device__ int   g_lo[NHEADS];
__device__ int   g_hi[NHEADS];

// ---------------- helpers ----------------
__device__ __forceinline__ unsigned f2tf32(float x) {
    unsigned u; asm("cvt.rna.tf32.f32 %0, %1;\n" : "=r"(u) : "f"(x)); return u;
}

__device__ __forceinline__ void mma_tf32(float d[4], const unsigned a[4], const unsigned b[2]) {
    asm volatile(
        "mma.sync.aligned.m16n8k8.row.col.f32.tf32.tf32.f32 "
        "{%0,%1,%2,%3}, {%4,%5,%6,%7}, {%8,%9}, {%0,%1,%2,%3};\n"
        : "+f"(d[0]), "+f"(d[1]), "+f"(d[2]), "+f"(d[3])
        : "r"(a[0]), "r"(a[1]), "r"(a[2]), "r"(a[3]), "r"(b[0]), "r"(b[1]));
}

// Load 64 rows x 32 k tile into [row][k] pitch PITCH_MK, optional mask over k. 128 thr.
__device__ __forceinline__ void load_mk(unsigned* T, const float* __restrict__ g, size_t ld,
                                        int k0, int tid, const float* __restrict__ mask) {
    #pragma unroll
    for (int it = 0; it < 4; it++) {
        int i = tid + it * 128;
        int r = i >> 3, q = (i & 7) * 4;
        float4 v = *(const float4*)(g + (size_t)r * ld + k0 + q);
        if (mask) {
            v.x *= mask[k0 + q];     v.y *= mask[k0 + q + 1];
            v.z *= mask[k0 + q + 2]; v.w *= mask[k0 + q + 3];
        }
        uint4 u = make_uint4(f2tf32(v.x), f2tf32(v.y), f2tf32(v.z), f2tf32(v.w));
        *(uint4*)(T + r * PITCH_MK + q) = u;
    }
}

// Load 32 k x 64 n tile into [k][n] pitch PITCH_KN, optional mask over n (local). 128 thr.
__device__ __forceinline__ void load_kn(unsigned* T, const float* __restrict__ g, size_t ld,
                                        int k0, int tid, const float* __restrict__ maskn) {
    #pragma unroll
    for (int it = 0; it < 4; it++) {
        int i = tid + it * 128;
        int k = i >> 4, q = (i & 15) * 4;
        float4 v = *(const float4*)(g + (size_t)(k0 + k) * ld + q);
        if (maskn) {
            v.x *= maskn[q];     v.y *= maskn[q + 1];
            v.z *= maskn[q + 2]; v.w *= maskn[q + 3];
        }
        uint4 u = make_uint4(f2tf32(v.x), f2tf32(v.y), f2tf32(v.z), f2tf32(v.w));
        *(uint4*)(T + k * PITCH_KN + q) = u;
    }
}

// 2x2-warp 64x64 GEMM tile step (BK=32). B in [k][n] pitch PITCH_KN.
__device__ __forceinline__ void mma_tile_kn(float c[2][4][4], const unsigned* As, const unsigned* Bs,
                                            int wm, int wn, int g, int tig) {
    #pragma unroll
    for (int kq = 0; kq < 32; kq += 8) {
        unsigned a[2][4], b[4][2];
        #pragma unroll
        for (int mt = 0; mt < 2; mt++) {
            int mr = wm * 32 + mt * 16;
            a[mt][0] = As[(mr + g) * PITCH_MK + kq + tig];
            a[mt][1] = As[(mr + g + 8) * PITCH_MK + kq + tig];
            a[mt][2] = As[(mr + g) * PITCH_MK + kq + tig + 4];
            a[mt][3] = As[(mr + g + 8) * PITCH_MK + kq + tig + 4];
        }
        #pragma unroll
        for (int nt = 0; nt < 4; nt++) {
            int nr = wn * 32 + nt * 8;
            b[nt][0] = Bs[(kq + tig) * PITCH_KN + nr + g];
            b[nt][1] = Bs[(kq + tig + 4) * PITCH_KN + nr + g];
        }
        #pragma unroll
        for (int mt = 0; mt < 2; mt++)
            #pragma unroll
            for (int nt = 0; nt < 4; nt++)
                mma_tf32(c[mt][nt], a[mt], b[nt]);
    }
}

// ---------------- prep ----------------
__global__ void prep_kernel(const float* __restrict__ hw) {
    __shared__ float s_start[NHEADS], s_dim[NHEADS];
    int tid = threadIdx.x;
    if (tid == 0) {
        float m = hw[0];
        for (int h = 1; h < NHEADS; h++) m = fmaxf(m, hw[h]);
        float e[NHEADS]; float sum = 0.f;
        for (int h = 0; h < NHEADS; h++) { e[h] = expf(hw[h] - m); sum += e[h]; }
        float start = 0.f;
        for (int h = 0; h < NHEADS; h++) {
            float gate = e[h] / sum;
            float dim = 16.f + gate * (float)(D_MODEL - 16 * NHEADS);
            if (dim < 0.f) dim = 0.f;
            s_start[h] = start; s_dim[h] = dim;
            g_inv_scale[h] = rsqrtf(dim + 1e-6f);
            start += dim;
        }
    }
    __syncthreads();
    if (tid < D_MODEL) {
        float pos = (float)tid;
        for (int h = 0; h < NHEADS; h++) {
            float l = 1.f / (1.f + expf(-(pos - s_start[h]) * 10.f));
            float r = 1.f / (1.f + expf(-(s_start[h] + s_dim[h] - pos) * 10.f));
            g_mask[h][tid] = l * r;
        }
    }
    __syncthreads();
    if (tid == 0) {
        for (int h = 0; h < NHEADS; h++) {
            int lo = D_MODEL, hi = 0;
            for (int d = 0; d < D_MODEL; d++)
                if (g_mask[h][d] > 1e-6f) { if (d < lo) lo = d; hi = d + 1; }
            if (lo >= hi) { lo = 0; hi = 0; }
            g_lo[h] = lo; g_hi[h] = hi;
        }
    }
}

// ---------------- qkv = query @ Wqkv + bqkv ----------------
__global__ __launch_bounds__(128) void qkv_gemm(const float* __restrict__ A,
                                                const float* __restrict__ W,
                                                const float* __restrict__ bias) {
    __shared__ unsigned As[64 * PITCH_MK];
    __shared__ unsigned Bs[32 * PITCH_KN];
    int bm = blockIdx.y * 64, bn = blockIdx.x * 64;
    int tid = threadIdx.x, w = tid >> 5, lane = tid & 31;
    int wm = w >> 1, wn = w & 1, g = lane >> 2, tig = lane & 3;
    float c[2][4][4] = {};
    for (int k0 = 0; k0 < D_MODEL; k0 += 32) {
        load_mk(As, A + (size_t)bm * D_MODEL, D_MODEL, k0, tid, nullptr);
        load_kn(Bs, W + bn, N3, k0, tid, nullptr);
        __syncthreads();
        mma_tile_kn(c, As, Bs, wm, wn, g, tig);
        __syncthreads();
    }
    #pragma unroll
    for (int mt = 0; mt < 2; mt++)
        #pragma unroll
        for (int nt = 0; nt < 4; nt++) {
            int row = bm + wm * 32 + mt * 16 + g;
            int col = bn + wn * 32 + nt * 8 + tig * 2;
            g_qkv[(size_t)row * N3 + col]           = c[mt][nt][0] + bias[col];
            g_qkv[(size_t)row * N3 + col + 1]       = c[mt][nt][1] + bias[col + 1];
            g_qkv[(size_t)(row + 8) * N3 + col]     = c[mt][nt][2] + bias[col];
            g_qkv[(size_t)(row + 8) * N3 + col + 1] = c[mt][nt][3] + bias[col + 1];
        }
}

// ---------------- zero ctx ----------------
__global__ void zero_ctx() {
    size_t i = (size_t)blockIdx.x * blockDim.x + threadIdx.x;
    ((float4*)g_ctx)[i] = make_float4(0.f, 0.f, 0.f, 0.f);
}

// ---------------- flash: fused scores+softmax+PV, per (h,b,t-tile,d-chunk) ----------------
__global__ __launch_bounds__(128) void flash_kernel(const unsigned char* __restrict__ kpm) {
    __shared__ unsigned SQ[64 * PITCH_MK];   // Q k-tile, later reused for P half-tile
    __shared__ unsigned SK[64 * PITCH_MK];   // K k-tile
    __shared__ unsigned SV[32 * PITCH_KN];   // V half-tile (32 s x 64 d)
    int z = blockIdx.z, h = z >> 2, b = z & 3;
    int d0 = blockIdx.x * 64, t0 = blockIdx.y * 64;
    if (g_hi[h] <= d0 || g_lo[h] >= d0 + 64) return;   // d-chunk outside head window
    int klo = g_lo[h] & ~31;
    int khi = g_hi[h] + 31; khi &= ~31; if (khi > D_MODEL) khi = D_MODEL;
    float invs = g_inv_scale[h];
    const float* qb = g_qkv + (size_t)b * TSEQ * N3;
    const float* kb = qb + D_MODEL;
    const float* vb = qb + 2 * D_MODEL;
    const float* mask  = g_mask[h];
    const float* maskn = g_mask[h] + d0;
    const unsigned char* kp = kpm + b * TSEQ;
    int tid = threadIdx.x, w = tid >> 5, lane = tid & 31, g = lane >> 2, tig = lane & 3;
    int mr = w * 16;                                    // each warp owns 16 t-rows

    float o[8][4] = {};
    float m0 = -1e30f, m1 = -1e30f, l0 = 0.f, l1 = 0.f;

    for (int s0 = 0; s0 < TSEQ; s0 += 64) {
        // ---- S tile: (q.m).(k.m) over the head's k-window ----
        float c[8][4] = {};
        for (int k0 = klo; k0 < khi; k0 += 32) {
            load_mk(SQ, qb + (size_t)t0 * N3, N3, k0, tid, mask);
            load_mk(SK, kb + (size_t)s0 * N3, N3, k0, tid, mask);
            __syncthreads();
            #pragma unroll
            for (int kq = 0; kq < 32; kq += 8) {
                unsigned a[4];
                a[0] = SQ[(mr + g) * PITCH_MK + kq + tig];
                a[1] = SQ[(mr + g + 8) * PITCH_MK + kq + tig];
                a[2] = SQ[(mr + g) * PITCH_MK + kq + tig + 4];
                a[3] = SQ[(mr + g + 8) * PITCH_MK + kq + tig + 4];
                #pragma unroll
                for (int nt = 0; nt < 8; nt++) {
                    unsigned bf[2];
                    bf[0] = SK[(nt * 8 + g) * PITCH_MK + kq + tig];
                    bf[1] = SK[(nt * 8 + g) * PITCH_MK + kq + tig + 4];
                    mma_tf32(c[nt], a, bf);
                }
            }
            __syncthreads();
        }
        // ---- scale + key-padding mask ----
        #pragma unroll
        for (int nt = 0; nt < 8; nt++) {
            int col = s0 + nt * 8 + tig * 2;
            bool p0 = kp[col] != 0, p1 = kp[col + 1] != 0;
            c[nt][0] = p0 ? -1e9f : c[nt][0] * invs;
            c[nt][1] = p1 ? -1e9f : c[nt][1] * invs;
            c[nt][2] = p0 ? -1e9f : c[nt][2] * invs;
            c[nt][3] = p1 ? -1e9f : c[nt][3] * invs;
        }
        // ---- online softmax update (rows g and g+8) ----
        float mx0 = -1e30f, mx1 = -1e30f;
        #pragma unroll
        for (int nt = 0; nt < 8; nt++) {
            mx0 = fmaxf(mx0, fmaxf(c[nt][0], c[nt][1]));
            mx1 = fmaxf(mx1, fmaxf(c[nt][2], c[nt][3]));
        }
        mx0 = fmaxf(mx0, __shfl_xor_sync(0xffffffffu, mx0, 1));
        mx0 = fmaxf(mx0, __shfl_xor_sync(0xffffffffu, mx0, 2));
        mx1 = fmaxf(mx1, __shfl_xor_sync(0xffffffffu, mx1, 1));
        mx1 = fmaxf(mx1, __shfl_xor_sync(0xffffffffu, mx1, 2));
        float nm0 = fmaxf(m0, mx0), nm1 = fmaxf(m1, mx1);
        float al0 = __expf(m0 - nm0), al1 = __expf(m1 - nm1);
        m0 = nm0; m1 = nm1;
        float rs0 = 0.f, rs1 = 0.f;
        #pragma unroll
        for (int nt = 0; nt < 8; nt++) {
            c[nt][0] = __expf(c[nt][0] - m0); c[nt][1] = __expf(c[nt][1] - m0);
            c[nt][2] = __expf(c[nt][2] - m1); c[nt][3] = __expf(c[nt][3] - m1);
            rs0 += c[nt][0] + c[nt][1];
            rs1 += c[nt][2] + c[nt][3];
        }
        rs0 += __shfl_xor_sync(0xffffffffu, rs0, 1);
        rs0 += __shfl_xor_sync(0xffffffffu, rs0, 2);
        rs1 += __shfl_xor_sync(0xffffffffu, rs1, 1);
        rs1 += __shfl_xor_sync(0xffffffffu, rs1, 2);
        l0 = l0 * al0 + rs0;
        l1 = l1 * al1 + rs1;
        #pragma unroll
        for (int nt = 0; nt < 8; nt++) {
            o[nt][0] *= al0; o[nt][1] *= al0;
            o[nt][2] *= al1; o[nt][3] *= al1;
        }
        // ---- O += P @ (V.mask), in two 32-wide s-halves ----
        #pragma unroll
        for (int half = 0; half < 2; half++) {
            #pragma unroll
            for (int nt = 0; nt < 4; nt++) {
                int src = half * 4 + nt;
                int colp = nt * 8 + tig * 2;
                SQ[(mr + g) * PITCH_MK + colp]         = f2tf32(c[src][0]);
                SQ[(mr + g) * PITCH_MK + colp + 1]     = f2tf32(c[src][1]);
                SQ[(mr + g + 8) * PITCH_MK + colp]     = f2tf32(c[src][2]);
                SQ[(mr + g + 8) * PITCH_MK + colp + 1] = f2tf32(c[src][3]);
            }
            load_kn(SV, vb + d0, N3, s0 + half * 32, tid, maskn);
            __syncthreads();
            #pragma unroll
            for (int kq = 0; kq < 32; kq += 8) {
                unsigned a[4];
                a[0] = SQ[(mr + g) * PITCH_MK + kq + tig];
                a[1] = SQ[(mr + g + 8) * PITCH_MK + kq + tig];
                a[2] = SQ[(mr + g) * PITCH_MK + kq + tig + 4];
                a[3] = SQ[(mr + g + 8) * PITCH_MK + kq + tig + 4];
                #pragma unroll
                for (int nt = 0; nt < 8; nt++) {
                    unsigned bf[2];
                    bf[0] = SV[(kq + tig) * PITCH_KN + nt * 8 + g];
                    bf[1] = SV[(kq + tig + 4) * PITCH_KN + nt * 8 + g];
                    mma_tf32(o[nt], a, bf);
                }
            }
            __syncthreads();
        }
    }
    // ---- epilogue: normalize and accumulate into ctx ----
    float inv0 = 1.f / l0, inv1 = 1.f / l1;
    #pragma unroll
    for (int nt = 0; nt < 8; nt++) {
        int col = d0 + nt * 8 + tig * 2;
        size_t r0 = (size_t)(b * TSEQ + t0 + mr + g) * D_MODEL + col;
        size_t r1 = r0 + (size_t)8 * D_MODEL;
        atomicAdd(&g_ctx[r0],     o[nt][0] * inv0);
        atomicAdd(&g_ctx[r0 + 1], o[nt][1] * inv0);
        atomicAdd(&g_ctx[r1],     o[nt][2] * inv1);
        atomicAdd(&g_ctx[r1 + 1], o[nt][3] * inv1);
    }
}

// ---------------- res = ctx @ Wout + bout + query ----------------
__global__ __launch_bounds__(128) void out_gemm(const float* __restrict__ W,
                                                const float* __restrict__ bias,
                                                const float* __restrict__ query) {
    __shared__ unsigned As[64 * PITCH_MK];
    __shared__ unsigned Bs[32 * PITCH_KN];
    int bm = blockIdx.y * 64, bn = blockIdx.x * 64;
    int tid = threadIdx.x, w = tid >> 5, lane = tid & 31;
    int wm = w >> 1, wn = w & 1, g = lane >> 2, tig = lane & 3;
    float c[2][4][4] = {};
    for (int k0 = 0; k0 < D_MODEL; k0 += 32) {
        load_mk(As, g_ctx + (size_t)bm * D_MODEL, D_MODEL, k0, tid, nullptr);
        load_kn(Bs, W + bn, D_MODEL, k0, tid, nullptr);
        __syncthreads();
        mma_tile_kn(c, As, Bs, wm, wn, g, tig);
        __syncthreads();
    }
    #pragma unroll
    for (int mt = 0; mt < 2; mt++)
        #pragma unroll
        for (int nt = 0; nt < 4; nt++) {
            int row = bm + wm * 32 + mt * 16 + g;
            int col = bn + wn * 32 + nt * 8 + tig * 2;
            size_t i0 = (size_t)row * D_MODEL + col;
            size_t i2 = (size_t)(row + 8) * D_MODEL + col;
            g_res[i0]     = c[mt][nt][0] + bias[col]     + query[i0];
            g_res[i0 + 1] = c[mt][nt][1] + bias[col + 1] + query[i0 + 1];
            g_res[i2]     = c[mt][nt][2] + bias[col]     + query[i2];
            g_res[i2 + 1] = c[mt][nt][3] + bias[col + 1] + query[i2 + 1];
        }
}

// ---------------- layernorm ----------------
__global__ void ln_kernel(const float* __restrict__ gamma, const float* __restrict__ beta,
                          float* __restrict__ out) {
    __shared__ float shs[8];
    __shared__ float shq[8];
    int row = blockIdx.x;
    const float* x = g_res + (size_t)row * D_MODEL;
    int tid = threadIdx.x;
    float v0 = x[tid], v1 = x[tid + 256];
    float s = v0 + v1, sq = v0 * v0 + v1 * v1;
    #pragma unroll
    for (int o = 16; o > 0; o >>= 1) {
        s  += __shfl_xor_sync(0xffffffffu, s, o);
        sq += __shfl_xor_sync(0xffffffffu, sq, o);
    }
    if ((tid & 31) == 0) { shs[tid >> 5] = s; shq[tid >> 5] = sq; }
    __syncthreads();
    s = 0.f; sq = 0.f;
    #pragma unroll
    for (int w = 0; w < 8; w++) { s += shs[w]; sq += shq[w]; }
    float mu = s * (1.f / D_MODEL);
    float var = sq * (1.f / D_MODEL) - mu * mu;
    float inv = rsqrtf(var + 1e-5f);
    out[(size_t)row * D_MODEL + tid]       = (v0 - mu) * inv * gamma[tid] + beta[tid];
    out[(size_t)row * D_MODEL + tid + 256] = (v1 - mu) * inv * gamma[tid + 256] + beta[tid + 256];
}

// ---------------- launch ----------------
extern "C" void kernel_launch(void* const* d_in, const int* in_sizes, int n_in,
                              void* d_out, int out_size) {
    const float*         query = (const float*)d_in[0];
    const float*         hw    = (const float*)d_in[1];
    const float*         Wqkv  = (const float*)d_in[2];
    const float*         bqkv  = (const float*)d_in[3];
    const float*         Wout  = (const float*)d_in[4];
    const float*         bout  = (const float*)d_in[5];
    const float*         gamma = (const float*)d_in[6];
    const float*         beta  = (const float*)d_in[7];
    const unsigned char* kpm   = (const unsigned char*)d_in[8];
    float* out = (float*)d_out;

    prep_kernel<<<1, 512>>>(hw);
    qkv_gemm<<<dim3(N3 / 64, M_TOTAL / 64), 128>>>(query, Wqkv, bqkv);
    zero_ctx<<<(M_TOTAL * D_MODEL / 4) / 256, 256>>>();
    flash_kernel<<<dim3(D_MODEL / 64, TSEQ / 64, NHEADS * BATCH), 128>>>(kpm);
    out_gemm<<<dim3(D_MODEL / 64, M_TOTAL / 64), 128>>>(Wout, bout, query);
    ln_kernel<<<M_TOTAL, 256>>>(gamma, beta, out);
}

// round 4
// speedup vs baseline: 3.3375x; 1.0899x over previous
#include <cuda_runtime.h>
#include <math.h>
#include <stdint.h>

#define D_MODEL 512
#define NHEADS  8
#define TSEQ    1024
#define BATCH   4
#define M_TOTAL 4096
#define N3      1536
#define KSTR    448      /* max packed window: 14 chunks of 32 */
#define DCHUNKS 8

#define PITCH    40      /* unified [mn][k-pair-permuted] smem pitch (words) */
#define PITCH_MK 36      /* legacy GEMM pitches (qkv/out) */
#define PITCH_KN 72

// ---------------- scratch ----------------
__device__ float g_qkv[(size_t)M_TOTAL * N3];
__device__ float g_ctx[(size_t)M_TOTAL * D_MODEL];
__device__ float g_res[(size_t)M_TOTAL * D_MODEL];
__device__ float g_qp[(size_t)NHEADS * M_TOTAL * KSTR];   // masked tf32 permuted Q
__device__ float g_kp[(size_t)NHEADS * M_TOTAL * KSTR];   // masked tf32 permuted K
__device__ float g_vp[(size_t)NHEADS * DCHUNKS * BATCH * 64 * TSEQ]; // V^T masked tf32 perm
__device__ float g_mask[NHEADS][D_MODEL];
__device__ float g_inv_scale[NHEADS];
__device__ int   g_lo[NHEADS];
__device__ int   g_hi[NHEADS];

// ---------------- helpers ----------------
__device__ __forceinline__ unsigned f2tf32(float x) {
    unsigned u; asm("cvt.rna.tf32.f32 %0, %1;\n" : "=r"(u) : "f"(x)); return u;
}
__device__ __forceinline__ void mma_tf32(float d[4], const unsigned a[4], const unsigned b[2]) {
    asm volatile(
        "mma.sync.aligned.m16n8k8.row.col.f32.tf32.tf32.f32 "
        "{%0,%1,%2,%3}, {%4,%5,%6,%7}, {%8,%9}, {%0,%1,%2,%3};\n"
        : "+f"(d[0]), "+f"(d[1]), "+f"(d[2]), "+f"(d[3])
        : "r"(a[0]), "r"(a[1]), "r"(a[2]), "r"(a[3]), "r"(b[0]), "r"(b[1]));
}
__device__ __forceinline__ void cp16(void* s, const void* gm) {
    unsigned sa = (unsigned)__cvta_generic_to_shared(s);
    asm volatile("cp.async.cg.shared.global [%0], [%1], 16;\n" :: "r"(sa), "l"(gm));
}
#define CP_COMMIT asm volatile("cp.async.commit_group;\n")
#define CP_WAIT0  asm volatile("cp.async.wait_group 0;\n")

// ---------------- prep ----------------
__global__ void prep_kernel(const float* __restrict__ hw) {
    __shared__ float s_start[NHEADS], s_dim[NHEADS];
    int tid = threadIdx.x;
    if (tid == 0) {
        float m = hw[0];
        for (int h = 1; h < NHEADS; h++) m = fmaxf(m, hw[h]);
        float e[NHEADS]; float sum = 0.f;
        for (int h = 0; h < NHEADS; h++) { e[h] = expf(hw[h] - m); sum += e[h]; }
        float start = 0.f;
        for (int h = 0; h < NHEADS; h++) {
            float gate = e[h] / sum;
            float dim = 16.f + gate * (float)(D_MODEL - 16 * NHEADS);
            if (dim < 0.f) dim = 0.f;
            s_start[h] = start; s_dim[h] = dim;
            g_inv_scale[h] = rsqrtf(dim + 1e-6f);
            start += dim;
        }
    }
    __syncthreads();
    if (tid < D_MODEL) {
        float pos = (float)tid;
        for (int h = 0; h < NHEADS; h++) {
            float l = 1.f / (1.f + expf(-(pos - s_start[h]) * 10.f));
            float r = 1.f / (1.f + expf(-(s_start[h] + s_dim[h] - pos) * 10.f));
            g_mask[h][tid] = l * r;
        }
    }
    __syncthreads();
    if (tid == 0) {
        for (int h = 0; h < NHEADS; h++) {
            int lo = D_MODEL, hi = 0;
            for (int d = 0; d < D_MODEL; d++)
                if (g_mask[h][d] > 1e-6f) { if (d < lo) lo = d; hi = d + 1; }
            if (lo >= hi) { lo = 0; hi = 0; }
            g_lo[h] = lo; g_hi[h] = hi;
        }
    }
}

// ---------------- legacy GEMM helpers (qkv / out) ----------------
__device__ __forceinline__ void load_mk(unsigned* T, const float* __restrict__ g, size_t ld,
                                        int k0, int tid) {
    #pragma unroll
    for (int it = 0; it < 4; it++) {
        int i = tid + it * 128;
        int r = i >> 3, q = (i & 7) * 4;
        float4 v = *(const float4*)(g + (size_t)r * ld + k0 + q);
        uint4 u = make_uint4(f2tf32(v.x), f2tf32(v.y), f2tf32(v.z), f2tf32(v.w));
        *(uint4*)(T + r * PITCH_MK + q) = u;
    }
}
__device__ __forceinline__ void load_kn(unsigned* T, const float* __restrict__ g, size_t ld,
                                        int k0, int tid) {
    #pragma unroll
    for (int it = 0; it < 4; it++) {
        int i = tid + it * 128;
        int k = i >> 4, q = (i & 15) * 4;
        float4 v = *(const float4*)(g + (size_t)(k0 + k) * ld + q);
        uint4 u = make_uint4(f2tf32(v.x), f2tf32(v.y), f2tf32(v.z), f2tf32(v.w));
        *(uint4*)(T + k * PITCH_KN + q) = u;
    }
}
__device__ __forceinline__ void mma_tile_kn(float c[2][4][4], const unsigned* As, const unsigned* Bs,
                                            int wm, int wn, int g, int tig) {
    #pragma unroll
    for (int kq = 0; kq < 32; kq += 8) {
        unsigned a[2][4], b[4][2];
        #pragma unroll
        for (int mt = 0; mt < 2; mt++) {
            int mr = wm * 32 + mt * 16;
            a[mt][0] = As[(mr + g) * PITCH_MK + kq + tig];
            a[mt][1] = As[(mr + g + 8) * PITCH_MK + kq + tig];
            a[mt][2] = As[(mr + g) * PITCH_MK + kq + tig + 4];
            a[mt][3] = As[(mr + g + 8) * PITCH_MK + kq + tig + 4];
        }
        #pragma unroll
        for (int nt = 0; nt < 4; nt++) {
            int nr = wn * 32 + nt * 8;
            b[nt][0] = Bs[(kq + tig) * PITCH_KN + nr + g];
            b[nt][1] = Bs[(kq + tig + 4) * PITCH_KN + nr + g];
        }
        #pragma unroll
        for (int mt = 0; mt < 2; mt++)
            #pragma unroll
            for (int nt = 0; nt < 4; nt++)
                mma_tf32(c[mt][nt], a[mt], b[nt]);
    }
}

// ---------------- qkv = query @ Wqkv + bqkv ----------------
__global__ __launch_bounds__(128) void qkv_gemm(const float* __restrict__ A,
                                                const float* __restrict__ W,
                                                const float* __restrict__ bias) {
    __shared__ unsigned As[64 * PITCH_MK];
    __shared__ unsigned Bs[32 * PITCH_KN];
    int bm = blockIdx.y * 64, bn = blockIdx.x * 64;
    int tid = threadIdx.x, w = tid >> 5, lane = tid & 31;
    int wm = w >> 1, wn = w & 1, g = lane >> 2, tig = lane & 3;
    float c[2][4][4] = {};
    for (int k0 = 0; k0 < D_MODEL; k0 += 32) {
        load_mk(As, A + (size_t)bm * D_MODEL, D_MODEL, k0, tid);
        load_kn(Bs, W + bn, N3, k0, tid);
        __syncthreads();
        mma_tile_kn(c, As, Bs, wm, wn, g, tig);
        __syncthreads();
    }
    #pragma unroll
    for (int mt = 0; mt < 2; mt++)
        #pragma unroll
        for (int nt = 0; nt < 4; nt++) {
            int row = bm + wm * 32 + mt * 16 + g;
            int col = bn + wn * 32 + nt * 8 + tig * 2;
            g_qkv[(size_t)row * N3 + col]           = c[mt][nt][0] + bias[col];
            g_qkv[(size_t)row * N3 + col + 1]       = c[mt][nt][1] + bias[col + 1];
            g_qkv[(size_t)(row + 8) * N3 + col]     = c[mt][nt][2] + bias[col];
            g_qkv[(size_t)(row + 8) * N3 + col + 1] = c[mt][nt][3] + bias[col + 1];
        }
}

// ---------------- pack Q/K: masked * tf32 * pair-permuted over head window ----------------
__global__ __launch_bounds__(256) void pack_qk() {
    int h = blockIdx.y;
    int row0 = blockIdx.x * 64;
    int klo = g_lo[h] & ~31;
    int khi = (g_hi[h] + 31) & ~31; if (khi > D_MODEL) khi = D_MODEL;
    int per = (khi - klo) >> 2;          // float4s per row
    int tid = threadIdx.x;
    const float* mask = g_mask[h];
    #pragma unroll
    for (int which = 0; which < 2; which++) {
        float* dstbase = (which ? g_kp : g_qp) + ((size_t)h * M_TOTAL + row0) * KSTR;
        #pragma unroll
        for (int rb = 0; rb < 2; rb++) {
            int r = rb * 32 + (tid >> 3);
            const float* src = g_qkv + (size_t)(row0 + r) * N3 + which * D_MODEL;
            float* dst = dstbase + (size_t)r * KSTR;
            for (int f = (tid & 7); f < per; f += 8) {
                int k = klo + f * 4;
                float4 v = *(const float4*)(src + k);
                v.x *= mask[k];     v.y *= mask[k + 1];
                v.z *= mask[k + 2]; v.w *= mask[k + 3];
                int kw = f * 4;
                int gb = kw & ~7;
                int off = (kw & 4) ? 1 : 0;
                dst[gb + off]     = __uint_as_float(f2tf32(v.x));
                dst[gb + off + 2] = __uint_as_float(f2tf32(v.y));
                dst[gb + off + 4] = __uint_as_float(f2tf32(v.z));
                dst[gb + off + 6] = __uint_as_float(f2tf32(v.w));
            }
        }
    }
}

// ---------------- pack V: per (h, d-chunk, b): [d][s] masked tf32 s-permuted ----------------
__global__ __launch_bounds__(256) void pack_v() {
    int z = blockIdx.z, h = z >> 3, dc = z & 7;
    int b = blockIdx.y;
    int s0 = blockIdx.x * 64;
    int d0 = dc * 64;
    if (g_hi[h] <= d0 || g_lo[h] >= d0 + 64) return;
    __shared__ float tile[64][65];
    int tid = threadIdx.x;
    const float* mask = g_mask[h];
    const float* vsrc = g_qkv + (size_t)(b * TSEQ + s0) * N3 + 2 * D_MODEL + d0;
    for (int i = tid; i < 64 * 16; i += 256) {
        int s = i >> 4, dseg = (i & 15) * 4;
        float4 v = *(const float4*)(vsrc + (size_t)s * N3 + dseg);
        tile[dseg][s]     = v.x * mask[d0 + dseg];
        tile[dseg + 1][s] = v.y * mask[d0 + dseg + 1];
        tile[dseg + 2][s] = v.z * mask[d0 + dseg + 2];
        tile[dseg + 3][s] = v.w * mask[d0 + dseg + 3];
    }
    __syncthreads();
    float* dst = g_vp + ((size_t)z * BATCH + b) * 64 * TSEQ;
    for (int i = tid; i < 64 * 64; i += 256) {
        int d = i >> 6, sl = i & 63;
        int sp = (sl & ~7) + 2 * (sl & 3) + ((sl >> 2) & 1);
        dst[(size_t)d * TSEQ + s0 + sp] = __uint_as_float(f2tf32(tile[d][sl]));
    }
}

// ---------------- zero ctx ----------------
__global__ void zero_ctx() {
    size_t i = (size_t)blockIdx.x * blockDim.x + threadIdx.x;
    ((float4*)g_ctx)[i] = make_float4(0.f, 0.f, 0.f, 0.f);
}

// ---------------- flash ----------------
__global__ __launch_bounds__(128, 4) void flash_kernel(const unsigned char* __restrict__ kpm) {
    __shared__ unsigned SQ[64 * PITCH];        // Q chunk, reused for P
    __shared__ unsigned SK[64 * PITCH];
    __shared__ unsigned SV[2][64 * PITCH];     // V halves: 64 d-rows x 32 s
    int z = blockIdx.z, h = z >> 2, b = z & 3;
    int dc = blockIdx.x;
    int d0 = dc * 64, t0 = blockIdx.y * 64;
    if (g_hi[h] <= d0 || g_lo[h] >= d0 + 64) return;
    int klo = g_lo[h] & ~31;
    int khi = (g_hi[h] + 31) & ~31; if (khi > D_MODEL) khi = D_MODEL;
    int nch = (khi - klo) >> 5;
    float invs = g_inv_scale[h];
    const float* qp = g_qp + ((size_t)h * M_TOTAL + b * TSEQ + t0) * KSTR;
    const float* kp = g_kp + ((size_t)h * M_TOTAL + b * TSEQ) * KSTR;
    const float* vp = g_vp + ((size_t)(h * 8 + dc) * BATCH + b) * 64 * TSEQ;
    const unsigned char* kpb = kpm + b * TSEQ;
    int tid = threadIdx.x, w = tid >> 5, lane = tid & 31, g = lane >> 2, tig = lane & 3;
    int mr = w * 16;

    float o[8][4] = {};
    float m0 = -1e30f, m1 = -1e30f, l0 = 0.f, l1 = 0.f;

    for (int s0 = 0; s0 < TSEQ; s0 += 64) {
        // prefetch both V halves for this KV tile
        #pragma unroll
        for (int half = 0; half < 2; half++)
            #pragma unroll
            for (int it = 0; it < 4; it++) {
                int i = tid + it * 128;
                int r = i >> 3, seg = (i & 7) * 4;
                cp16(&SV[half][r * PITCH + seg], vp + (size_t)r * TSEQ + s0 + half * 32 + seg);
            }
        CP_COMMIT;

        // ---- S = Qm . Km over head window ----
        float c[8][4] = {};
        for (int ci = 0; ci < nch; ci++) {
            #pragma unroll
            for (int it = 0; it < 4; it++) {
                int i = tid + it * 128;
                int r = i >> 3, seg = (i & 7) * 4;
                cp16(&SQ[r * PITCH + seg], qp + (size_t)r * KSTR + ci * 32 + seg);
                cp16(&SK[r * PITCH + seg], kp + (size_t)(s0 + r) * KSTR + ci * 32 + seg);
            }
            CP_COMMIT; CP_WAIT0;
            __syncthreads();
            #pragma unroll
            for (int kq = 0; kq < 32; kq += 8) {
                uint2 aA = *(const uint2*)&SQ[(mr + g) * PITCH + kq + 2 * tig];
                uint2 aB = *(const uint2*)&SQ[(mr + g + 8) * PITCH + kq + 2 * tig];
                unsigned a[4] = {aA.x, aB.x, aA.y, aB.y};
                #pragma unroll
                for (int nt = 0; nt < 8; nt++) {
                    uint2 bb = *(const uint2*)&SK[(nt * 8 + g) * PITCH + kq + 2 * tig];
                    unsigned bf[2] = {bb.x, bb.y};
                    mma_tf32(c[nt], a, bf);
                }
            }
            __syncthreads();
        }
        // ---- scale + key-padding ----
        #pragma unroll
        for (int nt = 0; nt < 8; nt++) {
            int col = s0 + nt * 8 + tig * 2;
            bool p0 = kpb[col] != 0, p1 = kpb[col + 1] != 0;
            c[nt][0] = p0 ? -1e9f : c[nt][0] * invs;
            c[nt][1] = p1 ? -1e9f : c[nt][1] * invs;
            c[nt][2] = p0 ? -1e9f : c[nt][2] * invs;
            c[nt][3] = p1 ? -1e9f : c[nt][3] * invs;
        }
        // ---- online softmax (rows g, g+8; reduce across tig lanes) ----
        float mx0 = -1e30f, mx1 = -1e30f;
        #pragma unroll
        for (int nt = 0; nt < 8; nt++) {
            mx0 = fmaxf(mx0, fmaxf(c[nt][0], c[nt][1]));
            mx1 = fmaxf(mx1, fmaxf(c[nt][2], c[nt][3]));
        }
        mx0 = fmaxf(mx0, __shfl_xor_sync(0xffffffffu, mx0, 1));
        mx0 = fmaxf(mx0, __shfl_xor_sync(0xffffffffu, mx0, 2));
        mx1 = fmaxf(mx1, __shfl_xor_sync(0xffffffffu, mx1, 1));
        mx1 = fmaxf(mx1, __shfl_xor_sync(0xffffffffu, mx1, 2));
        float nm0 = fmaxf(m0, mx0), nm1 = fmaxf(m1, mx1);
        float al0 = __expf(m0 - nm0), al1 = __expf(m1 - nm1);
        m0 = nm0; m1 = nm1;
        float rs0 = 0.f, rs1 = 0.f;
        #pragma unroll
        for (int nt = 0; nt < 8; nt++) {
            c[nt][0] = __expf(c[nt][0] - m0); c[nt][1] = __expf(c[nt][1] - m0);
            c[nt][2] = __expf(c[nt][2] - m1); c[nt][3] = __expf(c[nt][3] - m1);
            rs0 += c[nt][0] + c[nt][1];
            rs1 += c[nt][2] + c[nt][3];
        }
        rs0 += __shfl_xor_sync(0xffffffffu, rs0, 1);
        rs0 += __shfl_xor_sync(0xffffffffu, rs0, 2);
        rs1 += __shfl_xor_sync(0xffffffffu, rs1, 1);
        rs1 += __shfl_xor_sync(0xffffffffu, rs1, 2);
        l0 = l0 * al0 + rs0;
        l1 = l1 * al1 + rs1;
        #pragma unroll
        for (int nt = 0; nt < 8; nt++) {
            o[nt][0] *= al0; o[nt][1] *= al0;
            o[nt][2] *= al1; o[nt][3] *= al1;
        }
        // ---- O += P @ V^T, two 32-s halves; P rows are warp-private (no sync needed) ----
        int p0 = (tig < 2) ? 4 * tig : 4 * (tig - 2) + 1;
        #pragma unroll
        for (int half = 0; half < 2; half++) {
            #pragma unroll
            for (int nt = 0; nt < 4; nt++) {
                int src = half * 4 + nt;
                SQ[(mr + g) * PITCH + nt * 8 + p0]         = f2tf32(c[src][0]);
                SQ[(mr + g) * PITCH + nt * 8 + p0 + 2]     = f2tf32(c[src][1]);
                SQ[(mr + g + 8) * PITCH + nt * 8 + p0]     = f2tf32(c[src][2]);
                SQ[(mr + g + 8) * PITCH + nt * 8 + p0 + 2] = f2tf32(c[src][3]);
            }
            __syncwarp();
            #pragma unroll
            for (int kq = 0; kq < 32; kq += 8) {
                uint2 aA = *(const uint2*)&SQ[(mr + g) * PITCH + kq + 2 * tig];
                uint2 aB = *(const uint2*)&SQ[(mr + g + 8) * PITCH + kq + 2 * tig];
                unsigned a[4] = {aA.x, aB.x, aA.y, aB.y};
                #pragma unroll
                for (int nt = 0; nt < 8; nt++) {
                    uint2 bb = *(const uint2*)&SV[half][(nt * 8 + g) * PITCH + kq + 2 * tig];
                    unsigned bf[2] = {bb.x, bb.y};
                    mma_tf32(o[nt], a, bf);
                }
            }
            __syncwarp();
        }
        __syncthreads();   // all warps done with SQ/SV before next iteration's cp.async
    }
    // ---- epilogue ----
    float inv0 = 1.f / l0, inv1 = 1.f / l1;
    #pragma unroll
    for (int nt = 0; nt < 8; nt++) {
        int col = d0 + nt * 8 + tig * 2;
        size_t r0 = (size_t)(b * TSEQ + t0 + mr + g) * D_MODEL + col;
        size_t r1 = r0 + (size_t)8 * D_MODEL;
        atomicAdd(&g_ctx[r0],     o[nt][0] * inv0);
        atomicAdd(&g_ctx[r0 + 1], o[nt][1] * inv0);
        atomicAdd(&g_ctx[r1],     o[nt][2] * inv1);
        atomicAdd(&g_ctx[r1 + 1], o[nt][3] * inv1);
    }
}

// ---------------- res = ctx @ Wout + bout + query ----------------
__global__ __launch_bounds__(128) void out_gemm(const float* __restrict__ W,
                                                const float* __restrict__ bias,
                                                const float* __restrict__ query) {
    __shared__ unsigned As[64 * PITCH_MK];
    __shared__ unsigned Bs[32 * PITCH_KN];
    int bm = blockIdx.y * 64, bn = blockIdx.x * 64;
    int tid = threadIdx.x, w = tid >> 5, lane = tid & 31;
    int wm = w >> 1, wn = w & 1, g = lane >> 2, tig = lane & 3;
    float c[2][4][4] = {};
    for (int k0 = 0; k0 < D_MODEL; k0 += 32) {
        load_mk(As, g_ctx + (size_t)bm * D_MODEL, D_MODEL, k0, tid);
        load_kn(Bs, W + bn, D_MODEL, k0, tid);
        __syncthreads();
        mma_tile_kn(c, As, Bs, wm, wn, g, tig);
        __syncthreads();
    }
    #pragma unroll
    for (int mt = 0; mt < 2; mt++)
        #pragma unroll
        for (int nt = 0; nt < 4; nt++) {
            int row = bm + wm * 32 + mt * 16 + g;
            int col = bn + wn * 32 + nt * 8 + tig * 2;
            size_t i0 = (size_t)row * D_MODEL + col;
            size_t i2 = (size_t)(row + 8) * D_MODEL + col;
            g_res[i0]     = c[mt][nt][0] + bias[col]     + query[i0];
            g_res[i0 + 1] = c[mt][nt][1] + bias[col + 1] + query[i0 + 1];
            g_res[i2]     = c[mt][nt][2] + bias[col]     + query[i2];
            g_res[i2 + 1] = c[mt][nt][3] + bias[col + 1] + query[i2 + 1];
        }
}

// ---------------- layernorm ----------------
__global__ void ln_kernel(const float* __restrict__ gamma, const float* __restrict__ beta,
                          float* __restrict__ out) {
    __shared__ float shs[8];
    __shared__ float shq[8];
    int row = blockIdx.x;
    const float* x = g_res + (size_t)row * D_MODEL;
    int tid = threadIdx.x;
    float v0 = x[tid], v1 = x[tid + 256];
    float s = v0 + v1, sq = v0 * v0 + v1 * v1;
    #pragma unroll
    for (int o = 16; o > 0; o >>= 1) {
        s  += __shfl_xor_sync(0xffffffffu, s, o);
        sq += __shfl_xor_sync(0xffffffffu, sq, o);
    }
    if ((tid & 31) == 0) { shs[tid >> 5] = s; shq[tid >> 5] = sq; }
    __syncthreads();
    s = 0.f; sq = 0.f;
    #pragma unroll
    for (int w = 0; w < 8; w++) { s += shs[w]; sq += shq[w]; }
    float mu = s * (1.f / D_MODEL);
    float var = sq * (1.f / D_MODEL) - mu * mu;
    float inv = rsqrtf(var + 1e-5f);
    out[(size_t)row * D_MODEL + tid]       = (v0 - mu) * inv * gamma[tid] + beta[tid];
    out[(size_t)row * D_MODEL + tid + 256] = (v1 - mu) * inv * gamma[tid + 256] + beta[tid + 256];
}

// ---------------- launch ----------------
extern "C" void kernel_launch(void* const* d_in, const int* in_sizes, int n_in,
                              void* d_out, int out_size) {
    const float*         query = (const float*)d_in[0];
    const float*         hw    = (const float*)d_in[1];
    const float*         Wqkv  = (const float*)d_in[2];
    const float*         bqkv  = (const float*)d_in[3];
    const float*         Wout  = (const float*)d_in[4];
    const float*         bout  = (const float*)d_in[5];
    const float*         gamma = (const float*)d_in[6];
    const float*         beta  = (const float*)d_in[7];
    const unsigned char* kpm   = (const unsigned char*)d_in[8];
    float* out = (float*)d_out;

    prep_kernel<<<1, 512>>>(hw);
    qkv_gemm<<<dim3(N3 / 64, M_TOTAL / 64), 128>>>(query, Wqkv, bqkv);
    pack_qk<<<dim3(M_TOTAL / 64, NHEADS), 256>>>();
    pack_v<<<dim3(TSEQ / 64, BATCH, NHEADS * DCHUNKS), 256>>>();
    zero_ctx<<<(M_TOTAL * D_MODEL / 4) / 256, 256>>>();
    flash_kernel<<<dim3(DCHUNKS, TSEQ / 64, NHEADS * BATCH), 128>>>(kpm);
    out_gemm<<<dim3(D_MODEL / 64, M_TOTAL / 64), 128>>>(Wout, bout, query);
    ln_kernel<<<M_TOTAL, 256>>>(gamma, beta, out);
}

// round 5
// speedup vs baseline: 3.6348x; 1.0891x over previous
#include <cuda_runtime.h>
#include <math.h>
#include <stdint.h>

#define D_MODEL 512
#define NHEADS  8
#define TSEQ    1024
#define BATCH   4
#define M_TOTAL 4096
#define N3      1536
#define KSTR    448      /* max packed window: 14 chunks of 32 */
#define DCHUNKS 8

#define PITCH    40      /* [mn][k-pair-permuted] smem pitch (words), conflict-free */
#define PITCH_MK 36
#define PITCH_KN 72
#define FLASH_SMEM (6 * 64 * PITCH * 4)   /* 61440 bytes */

// ---------------- scratch ----------------
__device__ float g_qkv[(size_t)M_TOTAL * N3];
__device__ float g_ctx[(size_t)M_TOTAL * D_MODEL];
__device__ float g_res[(size_t)M_TOTAL * D_MODEL];
__device__ float g_qp[(size_t)NHEADS * M_TOTAL * KSTR];
__device__ float g_kp[(size_t)NHEADS * M_TOTAL * KSTR];
__device__ float g_vp[(size_t)NHEADS * DCHUNKS * BATCH * 64 * TSEQ];
__device__ float g_mask[NHEADS][D_MODEL];
__device__ float g_inv_scale[NHEADS];
__device__ int   g_lo[NHEADS];
__device__ int   g_hi[NHEADS];

// ---------------- helpers ----------------
__device__ __forceinline__ unsigned f2tf32(float x) {
    unsigned u; asm("cvt.rna.tf32.f32 %0, %1;\n" : "=r"(u) : "f"(x)); return u;
}
__device__ __forceinline__ void mma_tf32(float d[4], const unsigned a[4], const unsigned b[2]) {
    asm volatile(
        "mma.sync.aligned.m16n8k8.row.col.f32.tf32.tf32.f32 "
        "{%0,%1,%2,%3}, {%4,%5,%6,%7}, {%8,%9}, {%0,%1,%2,%3};\n"
        : "+f"(d[0]), "+f"(d[1]), "+f"(d[2]), "+f"(d[3])
        : "r"(a[0]), "r"(a[1]), "r"(a[2]), "r"(a[3]), "r"(b[0]), "r"(b[1]));
}
__device__ __forceinline__ void cp16(void* s, const void* gm) {
    unsigned sa = (unsigned)__cvta_generic_to_shared(s);
    asm volatile("cp.async.cg.shared.global [%0], [%1], 16;\n" :: "r"(sa), "l"(gm));
}
#define CP_COMMIT asm volatile("cp.async.commit_group;\n")
#define CP_WAIT0  asm volatile("cp.async.wait_group 0;\n")
#define CP_WAIT1  asm volatile("cp.async.wait_group 1;\n")

// ---------------- prep ----------------
__global__ void prep_kernel(const float* __restrict__ hw) {
    __shared__ float s_start[NHEADS], s_dim[NHEADS];
    int tid = threadIdx.x;
    if (tid == 0) {
        float m = hw[0];
        for (int h = 1; h < NHEADS; h++) m = fmaxf(m, hw[h]);
        float e[NHEADS]; float sum = 0.f;
        for (int h = 0; h < NHEADS; h++) { e[h] = expf(hw[h] - m); sum += e[h]; }
        float start = 0.f;
        for (int h = 0; h < NHEADS; h++) {
            float gate = e[h] / sum;
            float dim = 16.f + gate * (float)(D_MODEL - 16 * NHEADS);
            if (dim < 0.f) dim = 0.f;
            s_start[h] = start; s_dim[h] = dim;
            g_inv_scale[h] = rsqrtf(dim + 1e-6f);
            start += dim;
        }
    }
    __syncthreads();
    if (tid < D_MODEL) {
        float pos = (float)tid;
        for (int h = 0; h < NHEADS; h++) {
            float l = 1.f / (1.f + expf(-(pos - s_start[h]) * 10.f));
            float r = 1.f / (1.f + expf(-(s_start[h] + s_dim[h] - pos) * 10.f));
            g_mask[h][tid] = l * r;
        }
    }
    __syncthreads();
    if (tid == 0) {
        for (int h = 0; h < NHEADS; h++) {
            int lo = D_MODEL, hi = 0;
            for (int d = 0; d < D_MODEL; d++)
                if (g_mask[h][d] > 1e-6f) { if (d < lo) lo = d; hi = d + 1; }
            if (lo >= hi) { lo = 0; hi = 0; }
            g_lo[h] = lo; g_hi[h] = hi;
        }
    }
}

// ---------------- shared GEMM MMA step (B in [k][n] pitch PITCH_KN) ----------------
__device__ __forceinline__ void mma_tile_kn(float c[2][4][4], const unsigned* As, const unsigned* Bs,
                                            int wm, int wn, int g, int tig) {
    #pragma unroll
    for (int kq = 0; kq < 32; kq += 8) {
        unsigned a[2][4], b[4][2];
        #pragma unroll
        for (int mt = 0; mt < 2; mt++) {
            int mr = wm * 32 + mt * 16;
            a[mt][0] = As[(mr + g) * PITCH_MK + kq + tig];
            a[mt][1] = As[(mr + g + 8) * PITCH_MK + kq + tig];
            a[mt][2] = As[(mr + g) * PITCH_MK + kq + tig + 4];
            a[mt][3] = As[(mr + g + 8) * PITCH_MK + kq + tig + 4];
        }
        #pragma unroll
        for (int nt = 0; nt < 4; nt++) {
            int nr = wn * 32 + nt * 8;
            b[nt][0] = Bs[(kq + tig) * PITCH_KN + nr + g];
            b[nt][1] = Bs[(kq + tig + 4) * PITCH_KN + nr + g];
        }
        #pragma unroll
        for (int mt = 0; mt < 2; mt++)
            #pragma unroll
            for (int nt = 0; nt < 4; nt++)
                mma_tf32(c[mt][nt], a[mt], b[nt]);
    }
}

// ---------------- qkv = query @ Wqkv + bqkv (cp.async double-buffered, raw fp32->tf32) ----
__global__ __launch_bounds__(128) void qkv_gemm(const float* __restrict__ A,
                                                const float* __restrict__ W,
                                                const float* __restrict__ bias) {
    __shared__ float As[2][64 * PITCH_MK];
    __shared__ float Bs[2][32 * PITCH_KN];
    int bm = blockIdx.y * 64, bn = blockIdx.x * 64;
    int tid = threadIdx.x, w = tid >> 5, lane = tid & 31;
    int wm = w >> 1, wn = w & 1, g = lane >> 2, tig = lane & 3;
    float c[2][4][4] = {};
    const float* Abase = A + (size_t)bm * D_MODEL;
    const float* Wbase = W + bn;
    auto issue = [&](int buf, int k0) {
        #pragma unroll
        for (int it = 0; it < 4; it++) {
            int i = tid + it * 128;
            int r = i >> 3, q = (i & 7) * 4;
            cp16(&As[buf][r * PITCH_MK + q], Abase + (size_t)r * D_MODEL + k0 + q);
        }
        #pragma unroll
        for (int it = 0; it < 4; it++) {
            int i = tid + it * 128;
            int k = i >> 4, q = (i & 15) * 4;
            cp16(&Bs[buf][k * PITCH_KN + q], Wbase + (size_t)(k0 + k) * N3 + q);
        }
    };
    issue(0, 0); CP_COMMIT;
    const int NCH = D_MODEL / 32;
    for (int ci = 0; ci < NCH; ci++) {
        int cur = ci & 1;
        if (ci + 1 < NCH) { issue(cur ^ 1, (ci + 1) * 32); CP_COMMIT; CP_WAIT1; }
        else CP_WAIT0;
        __syncthreads();
        mma_tile_kn(c, (const unsigned*)As[cur], (const unsigned*)Bs[cur], wm, wn, g, tig);
        __syncthreads();
    }
    #pragma unroll
    for (int mt = 0; mt < 2; mt++)
        #pragma unroll
        for (int nt = 0; nt < 4; nt++) {
            int row = bm + wm * 32 + mt * 16 + g;
            int col = bn + wn * 32 + nt * 8 + tig * 2;
            g_qkv[(size_t)row * N3 + col]           = c[mt][nt][0] + bias[col];
            g_qkv[(size_t)row * N3 + col + 1]       = c[mt][nt][1] + bias[col + 1];
            g_qkv[(size_t)(row + 8) * N3 + col]     = c[mt][nt][2] + bias[col];
            g_qkv[(size_t)(row + 8) * N3 + col + 1] = c[mt][nt][3] + bias[col + 1];
        }
}

// ---------------- pack Q/K ----------------
__global__ __launch_bounds__(256) void pack_qk() {
    int h = blockIdx.y;
    int row0 = blockIdx.x * 64;
    int klo = g_lo[h] & ~31;
    int khi = (g_hi[h] + 31) & ~31; if (khi > D_MODEL) khi = D_MODEL;
    int per = (khi - klo) >> 2;
    int tid = threadIdx.x;
    const float* mask = g_mask[h];
    #pragma unroll
    for (int which = 0; which < 2; which++) {
        float* dstbase = (which ? g_kp : g_qp) + ((size_t)h * M_TOTAL + row0) * KSTR;
        #pragma unroll
        for (int rb = 0; rb < 2; rb++) {
            int r = rb * 32 + (tid >> 3);
            const float* src = g_qkv + (size_t)(row0 + r) * N3 + which * D_MODEL;
            float* dst = dstbase + (size_t)r * KSTR;
            for (int f = (tid & 7); f < per; f += 8) {
                int k = klo + f * 4;
                float4 v = *(const float4*)(src + k);
                v.x *= mask[k];     v.y *= mask[k + 1];
                v.z *= mask[k + 2]; v.w *= mask[k + 3];
                int kw = f * 4;
                int gb = kw & ~7;
                int off = (kw & 4) ? 1 : 0;
                dst[gb + off]     = __uint_as_float(f2tf32(v.x));
                dst[gb + off + 2] = __uint_as_float(f2tf32(v.y));
                dst[gb + off + 4] = __uint_as_float(f2tf32(v.z));
                dst[gb + off + 6] = __uint_as_float(f2tf32(v.w));
            }
        }
    }
}

// ---------------- pack V ----------------
__global__ __launch_bounds__(256) void pack_v() {
    int z = blockIdx.z, h = z >> 3, dc = z & 7;
    int b = blockIdx.y;
    int s0 = blockIdx.x * 64;
    int d0 = dc * 64;
    if (g_hi[h] <= d0 || g_lo[h] >= d0 + 64) return;
    __shared__ float tile[64][65];
    int tid = threadIdx.x;
    const float* mask = g_mask[h];
    const float* vsrc = g_qkv + (size_t)(b * TSEQ + s0) * N3 + 2 * D_MODEL + d0;
    for (int i = tid; i < 64 * 16; i += 256) {
        int s = i >> 4, dseg = (i & 15) * 4;
        float4 v = *(const float4*)(vsrc + (size_t)s * N3 + dseg);
        tile[dseg][s]     = v.x * mask[d0 + dseg];
        tile[dseg + 1][s] = v.y * mask[d0 + dseg + 1];
        tile[dseg + 2][s] = v.z * mask[d0 + dseg + 2];
        tile[dseg + 3][s] = v.w * mask[d0 + dseg + 3];
    }
    __syncthreads();
    float* dst = g_vp + ((size_t)z * BATCH + b) * 64 * TSEQ;
    for (int i = tid; i < 64 * 64; i += 256) {
        int d = i >> 6, sl = i & 63;
        int sp = (sl & ~7) + 2 * (sl & 3) + ((sl >> 2) & 1);
        dst[(size_t)d * TSEQ + s0 + sp] = __uint_as_float(f2tf32(tile[d][sl]));
    }
}

// ---------------- zero ctx ----------------
__global__ void zero_ctx() {
    size_t i = (size_t)blockIdx.x * blockDim.x + threadIdx.x;
    ((float4*)g_ctx)[i] = make_float4(0.f, 0.f, 0.f, 0.f);
}

// ---------------- flash (2-stage pipelined chunks, dynamic smem) ----------------
__global__ __launch_bounds__(128) void flash_kernel(const unsigned char* __restrict__ kpm) {
    extern __shared__ unsigned sm[];
    unsigned* SQb[2] = { sm,                sm + 64 * PITCH };
    unsigned* SKb[2] = { sm + 2 * 64 * PITCH, sm + 3 * 64 * PITCH };
    unsigned* SVh[2] = { sm + 4 * 64 * PITCH, sm + 5 * 64 * PITCH };
    int z = blockIdx.z, h = z >> 2, b = z & 3;
    int dc = blockIdx.x;
    int d0 = dc * 64, t0 = blockIdx.y * 64;
    if (g_hi[h] <= d0 || g_lo[h] >= d0 + 64) return;
    int klo = g_lo[h] & ~31;
    int khi = (g_hi[h] + 31) & ~31; if (khi > D_MODEL) khi = D_MODEL;
    int nch = (khi - klo) >> 5;
    float invs = g_inv_scale[h];
    const float* qp = g_qp + ((size_t)h * M_TOTAL + b * TSEQ + t0) * KSTR;
    const float* kp = g_kp + ((size_t)h * M_TOTAL + b * TSEQ) * KSTR;
    const float* vp = g_vp + ((size_t)(h * 8 + dc) * BATCH + b) * 64 * TSEQ;
    const unsigned char* kpb = kpm + b * TSEQ;
    int tid = threadIdx.x, w = tid >> 5, lane = tid & 31, g = lane >> 2, tig = lane & 3;
    int mr = w * 16;

    float o[8][4] = {};
    float m0 = -1e30f, m1 = -1e30f, l0 = 0.f, l1 = 0.f;

    for (int s0 = 0; s0 < TSEQ; s0 += 64) {
        // V prefetch (completes during S phase)
        #pragma unroll
        for (int half = 0; half < 2; half++)
            #pragma unroll
            for (int it = 0; it < 4; it++) {
                int i = tid + it * 128;
                int r = i >> 3, seg = (i & 7) * 4;
                cp16(&SVh[half][r * PITCH + seg], vp + (size_t)r * TSEQ + s0 + half * 32 + seg);
            }
        CP_COMMIT;

        auto issue_chunk = [&](int buf, int ci) {
            #pragma unroll
            for (int it = 0; it < 4; it++) {
                int i = tid + it * 128;
                int r = i >> 3, seg = (i & 7) * 4;
                cp16(&SQb[buf][r * PITCH + seg], qp + (size_t)r * KSTR + ci * 32 + seg);
                cp16(&SKb[buf][r * PITCH + seg], kp + (size_t)(s0 + r) * KSTR + ci * 32 + seg);
            }
        };
        issue_chunk(0, 0); CP_COMMIT;

        // ---- S = Qm . Km, pipelined ----
        float c[8][4] = {};
        for (int ci = 0; ci < nch; ci++) {
            int cur = ci & 1;
            if (ci + 1 < nch) { issue_chunk(cur ^ 1, ci + 1); CP_COMMIT; CP_WAIT1; }
            else CP_WAIT0;
            __syncthreads();
            const unsigned* SQ = SQb[cur];
            const unsigned* SK = SKb[cur];
            #pragma unroll
            for (int kq = 0; kq < 32; kq += 8) {
                uint2 aA = *(const uint2*)&SQ[(mr + g) * PITCH + kq + 2 * tig];
                uint2 aB = *(const uint2*)&SQ[(mr + g + 8) * PITCH + kq + 2 * tig];
                unsigned a[4] = {aA.x, aB.x, aA.y, aB.y};
                #pragma unroll
                for (int nt = 0; nt < 8; nt++) {
                    uint2 bb = *(const uint2*)&SK[(nt * 8 + g) * PITCH + kq + 2 * tig];
                    unsigned bf[2] = {bb.x, bb.y};
                    mma_tf32(c[nt], a, bf);
                }
            }
            __syncthreads();
        }
        // ---- scale + key-padding ----
        #pragma unroll
        for (int nt = 0; nt < 8; nt++) {
            int col = s0 + nt * 8 + tig * 2;
            bool p0 = kpb[col] != 0, p1 = kpb[col + 1] != 0;
            c[nt][0] = p0 ? -1e9f : c[nt][0] * invs;
            c[nt][1] = p1 ? -1e9f : c[nt][1] * invs;
            c[nt][2] = p0 ? -1e9f : c[nt][2] * invs;
            c[nt][3] = p1 ? -1e9f : c[nt][3] * invs;
        }
        // ---- online softmax ----
        float mx0 = -1e30f, mx1 = -1e30f;
        #pragma unroll
        for (int nt = 0; nt < 8; nt++) {
            mx0 = fmaxf(mx0, fmaxf(c[nt][0], c[nt][1]));
            mx1 = fmaxf(mx1, fmaxf(c[nt][2], c[nt][3]));
        }
        mx0 = fmaxf(mx0, __shfl_xor_sync(0xffffffffu, mx0, 1));
        mx0 = fmaxf(mx0, __shfl_xor_sync(0xffffffffu, mx0, 2));
        mx1 = fmaxf(mx1, __shfl_xor_sync(0xffffffffu, mx1, 1));
        mx1 = fmaxf(mx1, __shfl_xor_sync(0xffffffffu, mx1, 2));
        float nm0 = fmaxf(m0, mx0), nm1 = fmaxf(m1, mx1);
        float al0 = __expf(m0 - nm0), al1 = __expf(m1 - nm1);
        m0 = nm0; m1 = nm1;
        float rs0 = 0.f, rs1 = 0.f;
        #pragma unroll
        for (int nt = 0; nt < 8; nt++) {
            c[nt][0] = __expf(c[nt][0] - m0); c[nt][1] = __expf(c[nt][1] - m0);
            c[nt][2] = __expf(c[nt][2] - m1); c[nt][3] = __expf(c[nt][3] - m1);
            rs0 += c[nt][0] + c[nt][1];
            rs1 += c[nt][2] + c[nt][3];
        }
        rs0 += __shfl_xor_sync(0xffffffffu, rs0, 1);
        rs0 += __shfl_xor_sync(0xffffffffu, rs0, 2);
        rs1 += __shfl_xor_sync(0xffffffffu, rs1, 1);
        rs1 += __shfl_xor_sync(0xffffffffu, rs1, 2);
        l0 = l0 * al0 + rs0;
        l1 = l1 * al1 + rs1;
        #pragma unroll
        for (int nt = 0; nt < 8; nt++) {
            o[nt][0] *= al0; o[nt][1] *= al0;
            o[nt][2] *= al1; o[nt][3] *= al1;
        }
        // ---- O += P @ V^T (P into SQb[0], warp-private rows) ----
        unsigned* SP = SQb[0];
        int p0 = (tig < 2) ? 4 * tig : 4 * (tig - 2) + 1;
        #pragma unroll
        for (int half = 0; half < 2; half++) {
            #pragma unroll
            for (int nt = 0; nt < 4; nt++) {
                int src = half * 4 + nt;
                SP[(mr + g) * PITCH + nt * 8 + p0]         = f2tf32(c[src][0]);
                SP[(mr + g) * PITCH + nt * 8 + p0 + 2]     = f2tf32(c[src][1]);
                SP[(mr + g + 8) * PITCH + nt * 8 + p0]     = f2tf32(c[src][2]);
                SP[(mr + g + 8) * PITCH + nt * 8 + p0 + 2] = f2tf32(c[src][3]);
            }
            __syncwarp();
            #pragma unroll
            for (int kq = 0; kq < 32; kq += 8) {
                uint2 aA = *(const uint2*)&SP[(mr + g) * PITCH + kq + 2 * tig];
                uint2 aB = *(const uint2*)&SP[(mr + g + 8) * PITCH + kq + 2 * tig];
                unsigned a[4] = {aA.x, aB.x, aA.y, aB.y};
                #pragma unroll
                for (int nt = 0; nt < 8; nt++) {
                    uint2 bb = *(const uint2*)&SVh[half][(nt * 8 + g) * PITCH + kq + 2 * tig];
                    unsigned bf[2] = {bb.x, bb.y};
                    mma_tf32(o[nt], a, bf);
                }
            }
            __syncwarp();
        }
        __syncthreads();
    }
    // ---- epilogue ----
    float inv0 = 1.f / l0, inv1 = 1.f / l1;
    #pragma unroll
    for (int nt = 0; nt < 8; nt++) {
        int col = d0 + nt * 8 + tig * 2;
        size_t r0 = (size_t)(b * TSEQ + t0 + mr + g) * D_MODEL + col;
        size_t r1 = r0 + (size_t)8 * D_MODEL;
        atomicAdd(&g_ctx[r0],     o[nt][0] * inv0);
        atomicAdd(&g_ctx[r0 + 1], o[nt][1] * inv0);
        atomicAdd(&g_ctx[r1],     o[nt][2] * inv1);
        atomicAdd(&g_ctx[r1 + 1], o[nt][3] * inv1);
    }
}

// ---------------- res = ctx @ Wout + bout + query ----------------
__global__ __launch_bounds__(128) void out_gemm(const float* __restrict__ W,
                                                const float* __restrict__ bias,
                                                const float* __restrict__ query) {
    __shared__ float As[2][64 * PITCH_MK];
    __shared__ float Bs[2][32 * PITCH_KN];
    int bm = blockIdx.y * 64, bn = blockIdx.x * 64;
    int tid = threadIdx.x, w = tid >> 5, lane = tid & 31;
    int wm = w >> 1, wn = w & 1, g = lane >> 2, tig = lane & 3;
    float c[2][4][4] = {};
    const float* Abase = g_ctx + (size_t)bm * D_MODEL;
    const float* Wbase = W + bn;
    auto issue = [&](int buf, int k0) {
        #pragma unroll
        for (int it = 0; it < 4; it++) {
            int i = tid + it * 128;
            int r = i >> 3, q = (i & 7) * 4;
            cp16(&As[buf][r * PITCH_MK + q], Abase + (size_t)r * D_MODEL + k0 + q);
        }
        #pragma unroll
        for (int it = 0; it < 4; it++) {
            int i = tid + it * 128;
            int k = i >> 4, q = (i & 15) * 4;
            cp16(&Bs[buf][k * PITCH_KN + q], Wbase + (size_t)(k0 + k) * D_MODEL + q);
        }
    };
    issue(0, 0); CP_COMMIT;
    const int NCH = D_MODEL / 32;
    for (int ci = 0; ci < NCH; ci++) {
        int cur = ci & 1;
        if (ci + 1 < NCH) { issue(cur ^ 1, (ci + 1) * 32); CP_COMMIT; CP_WAIT1; }
        else CP_WAIT0;
        __syncthreads();
        mma_tile_kn(c, (const unsigned*)As[cur], (const unsigned*)Bs[cur], wm, wn, g, tig);
        __syncthreads();
    }
    #pragma unroll
    for (int mt = 0; mt < 2; mt++)
        #pragma unroll
        for (int nt = 0; nt < 4; nt++) {
            int row = bm + wm * 32 + mt * 16 + g;
            int col = bn + wn * 32 + nt * 8 + tig * 2;
            size_t i0 = (size_t)row * D_MODEL + col;
            size_t i2 = (size_t)(row + 8) * D_MODEL + col;
            g_res[i0]     = c[mt][nt][0] + bias[col]     + query[i0];
            g_res[i0 + 1] = c[mt][nt][1] + bias[col + 1] + query[i0 + 1];
            g_res[i2]     = c[mt][nt][2] + bias[col]     + query[i2];
            g_res[i2 + 1] = c[mt][nt][3] + bias[col + 1] + query[i2 + 1];
        }
}

// ---------------- layernorm ----------------
__global__ void ln_kernel(const float* __restrict__ gamma, const float* __restrict__ beta,
                          float* __restrict__ out) {
    __shared__ float shs[8];
    __shared__ float shq[8];
    int row = blockIdx.x;
    const float* x = g_res + (size_t)row * D_MODEL;
    int tid = threadIdx.x;
    float v0 = x[tid], v1 = x[tid + 256];
    float s = v0 + v1, sq = v0 * v0 + v1 * v1;
    #pragma unroll
    for (int o = 16; o > 0; o >>= 1) {
        s  += __shfl_xor_sync(0xffffffffu, s, o);
        sq += __shfl_xor_sync(0xffffffffu, sq, o);
    }
    if ((tid & 31) == 0) { shs[tid >> 5] = s; shq[tid >> 5] = sq; }
    __syncthreads();
    s = 0.f; sq = 0.f;
    #pragma unroll
    for (int w = 0; w < 8; w++) { s += shs[w]; sq += shq[w]; }
    float mu = s * (1.f / D_MODEL);
    float var = sq * (1.f / D_MODEL) - mu * mu;
    float inv = rsqrtf(var + 1e-5f);
    out[(size_t)row * D_MODEL + tid]       = (v0 - mu) * inv * gamma[tid] + beta[tid];
    out[(size_t)row * D_MODEL + tid + 256] = (v1 - mu) * inv * gamma[tid + 256] + beta[tid + 256];
}

// ---------------- launch ----------------
extern "C" void kernel_launch(void* const* d_in, const int* in_sizes, int n_in,
                              void* d_out, int out_size) {
    const float*         query = (const float*)d_in[0];
    const float*         hw    = (const float*)d_in[1];
    const float*         Wqkv  = (const float*)d_in[2];
    const float*         bqkv  = (const float*)d_in[3];
    const float*         Wout  = (const float*)d_in[4];
    const float*         bout  = (const float*)d_in[5];
    const float*         gamma = (const float*)d_in[6];
    const float*         beta  = (const float*)d_in[7];
    const unsigned char* kpm   = (const unsigned char*)d_in[8];
    float* out = (float*)d_out;

    cudaFuncSetAttribute(flash_kernel, cudaFuncAttributeMaxDynamicSharedMemorySize, FLASH_SMEM);

    prep_kernel<<<1, 512>>>(hw);
    qkv_gemm<<<dim3(N3 / 64, M_TOTAL / 64), 128>>>(query, Wqkv, bqkv);
    pack_qk<<<dim3(M_TOTAL / 64, NHEADS), 256>>>();
    pack_v<<<dim3(TSEQ / 64, BATCH, NHEADS * DCHUNKS), 256>>>();
    zero_ctx<<<(M_TOTAL * D_MODEL / 4) / 256, 256>>>();
    flash_kernel<<<dim3(DCHUNKS, TSEQ / 64, NHEADS * BATCH), 128, FLASH_SMEM>>>(kpm);
    out_gemm<<<dim3(D_MODEL / 64, M_TOTAL / 64), 128>>>(Wout, bout, query);
    ln_kernel<<<M_TOTAL, 256>>>(gamma, beta, out);
}

// round 6
// speedup vs baseline: 3.6919x; 1.0157x over previous
#include <cuda_runtime.h>
#include <math.h>
#include <stdint.h>

#define D_MODEL 512
#define NHEADS  8
#define TSEQ    1024
#define BATCH   4
#define M_TOTAL 4096
#define N3      1536
#define KSTR    448
#define DCHUNKS 8
#define RESCH   5        /* resident Q chunks */

#define PITCH    40      /* [mn][k-pair-permuted] smem pitch (words), conflict-free */
#define PITCH_MK 36
#define PITCH_KN 72
#define CHW      (64 * PITCH)                       /* words per chunk */
#define FLASH_SMEM ((RESCH + 6) * CHW * 4)          /* 5Q +2Qs +2K +2V = 112640 B */
#define LOG2E 1.4426950408889634f

// ---------------- scratch ----------------
__device__ float g_qkv[(size_t)M_TOTAL * N3];
__device__ float g_ctx[(size_t)M_TOTAL * D_MODEL];
__device__ float g_res[(size_t)M_TOTAL * D_MODEL];
__device__ float g_qp[(size_t)NHEADS * M_TOTAL * KSTR];
__device__ float g_kp[(size_t)NHEADS * M_TOTAL * KSTR];
__device__ float g_vp[(size_t)NHEADS * DCHUNKS * BATCH * 64 * TSEQ];
__device__ float g_mask[NHEADS][D_MODEL];
__device__ float g_inv_scale[NHEADS];
__device__ int   g_lo[NHEADS];
__device__ int   g_hi[NHEADS];

// ---------------- helpers ----------------
__device__ __forceinline__ unsigned f2tf32(float x) {
    unsigned u; asm("cvt.rna.tf32.f32 %0, %1;\n" : "=r"(u) : "f"(x)); return u;
}
__device__ __forceinline__ float ex2f(float x) {
    float y; asm("ex2.approx.f32 %0, %1;\n" : "=f"(y) : "f"(x)); return y;
}
__device__ __forceinline__ void mma_tf32(float d[4], const unsigned a[4], const unsigned b[2]) {
    asm volatile(
        "mma.sync.aligned.m16n8k8.row.col.f32.tf32.tf32.f32 "
        "{%0,%1,%2,%3}, {%4,%5,%6,%7}, {%8,%9}, {%0,%1,%2,%3};\n"
        : "+f"(d[0]), "+f"(d[1]), "+f"(d[2]), "+f"(d[3])
        : "r"(a[0]), "r"(a[1]), "r"(a[2]), "r"(a[3]), "r"(b[0]), "r"(b[1]));
}
__device__ __forceinline__ void cp16(void* s, const void* gm) {
    unsigned sa = (unsigned)__cvta_generic_to_shared(s);
    asm volatile("cp.async.cg.shared.global [%0], [%1], 16;\n" :: "r"(sa), "l"(gm));
}
#define CP_COMMIT asm volatile("cp.async.commit_group;\n")
#define CP_WAIT0  asm volatile("cp.async.wait_group 0;\n")
#define CP_WAIT1  asm volatile("cp.async.wait_group 1;\n")

// ---------------- prep ----------------
__global__ void prep_kernel(const float* __restrict__ hw) {
    __shared__ float s_start[NHEADS], s_dim[NHEADS];
    int tid = threadIdx.x;
    if (tid == 0) {
        float m = hw[0];
        for (int h = 1; h < NHEADS; h++) m = fmaxf(m, hw[h]);
        float e[NHEADS]; float sum = 0.f;
        for (int h = 0; h < NHEADS; h++) { e[h] = expf(hw[h] - m); sum += e[h]; }
        float start = 0.f;
        for (int h = 0; h < NHEADS; h++) {
            float gate = e[h] / sum;
            float dim = 16.f + gate * (float)(D_MODEL - 16 * NHEADS);
            if (dim < 0.f) dim = 0.f;
            s_start[h] = start; s_dim[h] = dim;
            g_inv_scale[h] = rsqrtf(dim + 1e-6f);
            start += dim;
        }
    }
    __syncthreads();
    if (tid < D_MODEL) {
        float pos = (float)tid;
        for (int h = 0; h < NHEADS; h++) {
            float l = 1.f / (1.f + expf(-(pos - s_start[h]) * 10.f));
            float r = 1.f / (1.f + expf(-(s_start[h] + s_dim[h] - pos) * 10.f));
            g_mask[h][tid] = l * r;
        }
    }
    __syncthreads();
    if (tid == 0) {
        for (int h = 0; h < NHEADS; h++) {
            int lo = D_MODEL, hi = 0;
            for (int d = 0; d < D_MODEL; d++)
                if (g_mask[h][d] > 1e-6f) { if (d < lo) lo = d; hi = d + 1; }
            if (lo >= hi) { lo = 0; hi = 0; }
            g_lo[h] = lo; g_hi[h] = hi;
        }
    }
}

// ---------------- shared GEMM MMA step (B in [k][n] pitch PITCH_KN) ----------------
__device__ __forceinline__ void mma_tile_kn(float c[2][4][4], const unsigned* As, const unsigned* Bs,
                                            int wm, int wn, int g, int tig) {
    #pragma unroll
    for (int kq = 0; kq < 32; kq += 8) {
        unsigned a[2][4], b[4][2];
        #pragma unroll
        for (int mt = 0; mt < 2; mt++) {
            int mr = wm * 32 + mt * 16;
            a[mt][0] = As[(mr + g) * PITCH_MK + kq + tig];
            a[mt][1] = As[(mr + g + 8) * PITCH_MK + kq + tig];
            a[mt][2] = As[(mr + g) * PITCH_MK + kq + tig + 4];
            a[mt][3] = As[(mr + g + 8) * PITCH_MK + kq + tig + 4];
        }
        #pragma unroll
        for (int nt = 0; nt < 4; nt++) {
            int nr = wn * 32 + nt * 8;
            b[nt][0] = Bs[(kq + tig) * PITCH_KN + nr + g];
            b[nt][1] = Bs[(kq + tig + 4) * PITCH_KN + nr + g];
        }
        #pragma unroll
        for (int mt = 0; mt < 2; mt++)
            #pragma unroll
            for (int nt = 0; nt < 4; nt++)
                mma_tf32(c[mt][nt], a[mt], b[nt]);
    }
}

// ---------------- qkv = query @ Wqkv + bqkv ----------------
__global__ __launch_bounds__(128) void qkv_gemm(const float* __restrict__ A,
                                                const float* __restrict__ W,
                                                const float* __restrict__ bias) {
    __shared__ float As[2][64 * PITCH_MK];
    __shared__ float Bs[2][32 * PITCH_KN];
    int bm = blockIdx.y * 64, bn = blockIdx.x * 64;
    int tid = threadIdx.x, w = tid >> 5, lane = tid & 31;
    int wm = w >> 1, wn = w & 1, g = lane >> 2, tig = lane & 3;
    float c[2][4][4] = {};
    const float* Abase = A + (size_t)bm * D_MODEL;
    const float* Wbase = W + bn;
    auto issue = [&](int buf, int k0) {
        #pragma unroll
        for (int it = 0; it < 4; it++) {
            int i = tid + it * 128;
            int r = i >> 3, q = (i & 7) * 4;
            cp16(&As[buf][r * PITCH_MK + q], Abase + (size_t)r * D_MODEL + k0 + q);
        }
        #pragma unroll
        for (int it = 0; it < 4; it++) {
            int i = tid + it * 128;
            int k = i >> 4, q = (i & 15) * 4;
            cp16(&Bs[buf][k * PITCH_KN + q], Wbase + (size_t)(k0 + k) * N3 + q);
        }
    };
    issue(0, 0); CP_COMMIT;
    const int NCH = D_MODEL / 32;
    for (int ci = 0; ci < NCH; ci++) {
        int cur = ci & 1;
        if (ci + 1 < NCH) { issue(cur ^ 1, (ci + 1) * 32); CP_COMMIT; CP_WAIT1; }
        else CP_WAIT0;
        __syncthreads();
        mma_tile_kn(c, (const unsigned*)As[cur], (const unsigned*)Bs[cur], wm, wn, g, tig);
        __syncthreads();
    }
    #pragma unroll
    for (int mt = 0; mt < 2; mt++)
        #pragma unroll
        for (int nt = 0; nt < 4; nt++) {
            int row = bm + wm * 32 + mt * 16 + g;
            int col = bn + wn * 32 + nt * 8 + tig * 2;
            g_qkv[(size_t)row * N3 + col]           = c[mt][nt][0] + bias[col];
            g_qkv[(size_t)row * N3 + col + 1]       = c[mt][nt][1] + bias[col + 1];
            g_qkv[(size_t)(row + 8) * N3 + col]     = c[mt][nt][2] + bias[col];
            g_qkv[(size_t)(row + 8) * N3 + col + 1] = c[mt][nt][3] + bias[col + 1];
        }
}

// ---------------- pack Q/K (Q additionally scaled by inv_scale*log2e) ----------------
__global__ __launch_bounds__(256) void pack_qk() {
    int h = blockIdx.y;
    int row0 = blockIdx.x * 64;
    int klo = g_lo[h] & ~31;
    int khi = (g_hi[h] + 31) & ~31; if (khi > D_MODEL) khi = D_MODEL;
    int per = (khi - klo) >> 2;
    int tid = threadIdx.x;
    const float* mask = g_mask[h];
    float qscale = g_inv_scale[h] * LOG2E;
    #pragma unroll
    for (int which = 0; which < 2; which++) {
        float* dstbase = (which ? g_kp : g_qp) + ((size_t)h * M_TOTAL + row0) * KSTR;
        float sc = which ? 1.f : qscale;
        #pragma unroll
        for (int rb = 0; rb < 2; rb++) {
            int r = rb * 32 + (tid >> 3);
            const float* src = g_qkv + (size_t)(row0 + r) * N3 + which * D_MODEL;
            float* dst = dstbase + (size_t)r * KSTR;
            for (int f = (tid & 7); f < per; f += 8) {
                int k = klo + f * 4;
                float4 v = *(const float4*)(src + k);
                v.x *= mask[k] * sc;     v.y *= mask[k + 1] * sc;
                v.z *= mask[k + 2] * sc; v.w *= mask[k + 3] * sc;
                int kw = f * 4;
                int gb = kw & ~7;
                int off = (kw & 4) ? 1 : 0;
                dst[gb + off]     = __uint_as_float(f2tf32(v.x));
                dst[gb + off + 2] = __uint_as_float(f2tf32(v.y));
                dst[gb + off + 4] = __uint_as_float(f2tf32(v.z));
                dst[gb + off + 6] = __uint_as_float(f2tf32(v.w));
            }
        }
    }
}

// ---------------- pack V ----------------
__global__ __launch_bounds__(256) void pack_v() {
    int z = blockIdx.z, h = z >> 3, dc = z & 7;
    int b = blockIdx.y;
    int s0 = blockIdx.x * 64;
    int d0 = dc * 64;
    if (g_hi[h] <= d0 || g_lo[h] >= d0 + 64) return;
    __shared__ float tile[64][65];
    int tid = threadIdx.x;
    const float* mask = g_mask[h];
    const float* vsrc = g_qkv + (size_t)(b * TSEQ + s0) * N3 + 2 * D_MODEL + d0;
    for (int i = tid; i < 64 * 16; i += 256) {
        int s = i >> 4, dseg = (i & 15) * 4;
        float4 v = *(const float4*)(vsrc + (size_t)s * N3 + dseg);
        tile[dseg][s]     = v.x * mask[d0 + dseg];
        tile[dseg + 1][s] = v.y * mask[d0 + dseg + 1];
        tile[dseg + 2][s] = v.z * mask[d0 + dseg + 2];
        tile[dseg + 3][s] = v.w * mask[d0 + dseg + 3];
    }
    __syncthreads();
    float* dst = g_vp + ((size_t)z * BATCH + b) * 64 * TSEQ;
    for (int i = tid; i < 64 * 64; i += 256) {
        int d = i >> 6, sl = i & 63;
        int sp = (sl & ~7) + 2 * (sl & 3) + ((sl >> 2) & 1);
        dst[(size_t)d * TSEQ + s0 + sp] = __uint_as_float(f2tf32(tile[d][sl]));
    }
}

// ---------------- zero ctx ----------------
__global__ void zero_ctx() {
    size_t i = (size_t)blockIdx.x * blockDim.x + threadIdx.x;
    ((float4*)g_ctx)[i] = make_float4(0.f, 0.f, 0.f, 0.f);
}

// ---------------- flash ----------------
__global__ __launch_bounds__(128) void flash_kernel(const unsigned char* __restrict__ kpm) {
    extern __shared__ unsigned sm[];
    unsigned* SQR = sm;                          // RESCH resident Q chunks
    unsigned* SQS = sm + RESCH * CHW;            // 2 streaming Q chunks
    unsigned* SKb[2] = { sm + (RESCH + 2) * CHW, sm + (RESCH + 3) * CHW };
    unsigned* SVh[2] = { sm + (RESCH + 4) * CHW, sm + (RESCH + 5) * CHW };
    int z = blockIdx.z, h = z >> 2, b = z & 3;
    int dc = blockIdx.x;
    int d0 = dc * 64, t0 = blockIdx.y * 64;
    if (g_hi[h] <= d0 || g_lo[h] >= d0 + 64) return;
    int klo = g_lo[h] & ~31;
    int khi = (g_hi[h] + 31) & ~31; if (khi > D_MODEL) khi = D_MODEL;
    int nch = (khi - klo) >> 5;
    const float* qp = g_qp + ((size_t)h * M_TOTAL + b * TSEQ + t0) * KSTR;
    const float* kp = g_kp + ((size_t)h * M_TOTAL + b * TSEQ) * KSTR;
    const float* vp = g_vp + ((size_t)(h * 8 + dc) * BATCH + b) * 64 * TSEQ;
    const unsigned char* kpb = kpm + b * TSEQ;
    int tid = threadIdx.x, w = tid >> 5, lane = tid & 31, g = lane >> 2, tig = lane & 3;
    int mr = w * 16;

    // resident Q (one cp.async group)
    int nres = nch < RESCH ? nch : RESCH;
    for (int ci = 0; ci < nres; ci++)
        #pragma unroll
        for (int it = 0; it < 4; it++) {
            int i = tid + it * 128;
            int r = i >> 3, seg = (i & 7) * 4;
            cp16(&SQR[ci * CHW + r * PITCH + seg], qp + (size_t)r * KSTR + ci * 32 + seg);
        }
    CP_COMMIT;

    float o[8][4] = {};
    float m0 = -1e30f, m1 = -1e30f, l0 = 0.f, l1 = 0.f;

    for (int s0 = 0; s0 < TSEQ; s0 += 64) {
        // V prefetch
        #pragma unroll
        for (int half = 0; half < 2; half++)
            #pragma unroll
            for (int it = 0; it < 4; it++) {
                int i = tid + it * 128;
                int r = i >> 3, seg = (i & 7) * 4;
                cp16(&SVh[half][r * PITCH + seg], vp + (size_t)r * TSEQ + s0 + half * 32 + seg);
            }
        CP_COMMIT;

        auto issue_chunk = [&](int buf, int ci) {
            #pragma unroll
            for (int it = 0; it < 4; it++) {
                int i = tid + it * 128;
                int r = i >> 3, seg = (i & 7) * 4;
                cp16(&SKb[buf][r * PITCH + seg], kp + (size_t)(s0 + r) * KSTR + ci * 32 + seg);
            }
            if (ci >= RESCH)
                #pragma unroll
                for (int it = 0; it < 4; it++) {
                    int i = tid + it * 128;
                    int r = i >> 3, seg = (i & 7) * 4;
                    cp16(&SQS[buf * CHW + r * PITCH + seg], qp + (size_t)r * KSTR + ci * 32 + seg);
                }
        };
        issue_chunk(0, 0); CP_COMMIT;

        // ---- S (already log2-scaled via packed Q) ----
        float c[8][4] = {};
        for (int ci = 0; ci < nch; ci++) {
            int cur = ci & 1;
            if (ci + 1 < nch) { issue_chunk(cur ^ 1, ci + 1); CP_COMMIT; CP_WAIT1; }
            else CP_WAIT0;
            __syncthreads();
            const unsigned* SQ = (ci < RESCH) ? (SQR + ci * CHW) : (SQS + cur * CHW);
            const unsigned* SK = SKb[cur];
            #pragma unroll
            for (int kq = 0; kq < 32; kq += 8) {
                uint2 aA = *(const uint2*)&SQ[(mr + g) * PITCH + kq + 2 * tig];
                uint2 aB = *(const uint2*)&SQ[(mr + g + 8) * PITCH + kq + 2 * tig];
                unsigned a[4] = {aA.x, aB.x, aA.y, aB.y};
                #pragma unroll
                for (int nt = 0; nt < 8; nt++) {
                    uint2 bb = *(const uint2*)&SK[(nt * 8 + g) * PITCH + kq + 2 * tig];
                    unsigned bf[2] = {bb.x, bb.y};
                    mma_tf32(c[nt], a, bf);
                }
            }
            __syncthreads();
        }
        // ---- key-padding (log2 domain) ----
        #pragma unroll
        for (int nt = 0; nt < 8; nt++) {
            int col = s0 + nt * 8 + tig * 2;
            if (kpb[col])     { c[nt][0] = -1e9f; c[nt][2] = -1e9f; }
            if (kpb[col + 1]) { c[nt][1] = -1e9f; c[nt][3] = -1e9f; }
        }
        // ---- running max update ----
        float mx0 = -1e30f, mx1 = -1e30f;
        #pragma unroll
        for (int nt = 0; nt < 8; nt++) {
            mx0 = fmaxf(mx0, fmaxf(c[nt][0], c[nt][1]));
            mx1 = fmaxf(mx1, fmaxf(c[nt][2], c[nt][3]));
        }
        mx0 = fmaxf(mx0, __shfl_xor_sync(0xffffffffu, mx0, 1));
        mx0 = fmaxf(mx0, __shfl_xor_sync(0xffffffffu, mx0, 2));
        mx1 = fmaxf(mx1, __shfl_xor_sync(0xffffffffu, mx1, 1));
        mx1 = fmaxf(mx1, __shfl_xor_sync(0xffffffffu, mx1, 2));
        float nm0 = fmaxf(m0, mx0), nm1 = fmaxf(m1, mx1);
        float al0 = ex2f(m0 - nm0), al1 = ex2f(m1 - nm1);
        m0 = nm0; m1 = nm1;
        if (al0 != 1.f || al1 != 1.f) {
            l0 *= al0; l1 *= al1;
            #pragma unroll
            for (int nt = 0; nt < 8; nt++) {
                o[nt][0] *= al0; o[nt][1] *= al0;
                o[nt][2] *= al1; o[nt][3] *= al1;
            }
        }
        // ---- interleaved exp (MUFU) + PV (tensor), two 32-s halves ----
        unsigned* SP = SKb[0];           // safe: all warps past last S sync; reloaded next s-tile
        int p0 = (tig < 2) ? 4 * tig : 4 * (tig - 2) + 1;
        float rs0 = 0.f, rs1 = 0.f;
        #pragma unroll
        for (int half = 0; half < 2; half++) {
            #pragma unroll
            for (int nt = 0; nt < 4; nt++) {
                int src = half * 4 + nt;
                float e0 = ex2f(c[src][0] - m0), e1 = ex2f(c[src][1] - m0);
                float e2 = ex2f(c[src][2] - m1), e3 = ex2f(c[src][3] - m1);
                rs0 += e0 + e1; rs1 += e2 + e3;
                SP[(mr + g) * PITCH + nt * 8 + p0]         = f2tf32(e0);
                SP[(mr + g) * PITCH + nt * 8 + p0 + 2]     = f2tf32(e1);
                SP[(mr + g + 8) * PITCH + nt * 8 + p0]     = f2tf32(e2);
                SP[(mr + g + 8) * PITCH + nt * 8 + p0 + 2] = f2tf32(e3);
            }
            __syncwarp();
            #pragma unroll
            for (int kq = 0; kq < 32; kq += 8) {
                uint2 aA = *(const uint2*)&SP[(mr + g) * PITCH + kq + 2 * tig];
                uint2 aB = *(const uint2*)&SP[(mr + g + 8) * PITCH + kq + 2 * tig];
                unsigned a[4] = {aA.x, aB.x, aA.y, aB.y};
                #pragma unroll
                for (int nt = 0; nt < 8; nt++) {
                    uint2 bb = *(const uint2*)&SVh[half][(nt * 8 + g) * PITCH + kq + 2 * tig];
                    unsigned bf[2] = {bb.x, bb.y};
                    mma_tf32(o[nt], a, bf);
                }
            }
            __syncwarp();
        }
        rs0 += __shfl_xor_sync(0xffffffffu, rs0, 1);
        rs0 += __shfl_xor_sync(0xffffffffu, rs0, 2);
        rs1 += __shfl_xor_sync(0xffffffffu, rs1, 1);
        rs1 += __shfl_xor_sync(0xffffffffu, rs1, 2);
        l0 += rs0; l1 += rs1;
        __syncthreads();
    }
    // ---- epilogue ----
    float inv0 = 1.f / l0, inv1 = 1.f / l1;
    #pragma unroll
    for (int nt = 0; nt < 8; nt++) {
        int col = d0 + nt * 8 + tig * 2;
        size_t r0 = (size_t)(b * TSEQ + t0 + mr + g) * D_MODEL + col;
        size_t r1 = r0 + (size_t)8 * D_MODEL;
        atomicAdd(&g_ctx[r0],     o[nt][0] * inv0);
        atomicAdd(&g_ctx[r0 + 1], o[nt][1] * inv0);
        atomicAdd(&g_ctx[r1],     o[nt][2] * inv1);
        atomicAdd(&g_ctx[r1 + 1], o[nt][3] * inv1);
    }
}

// ---------------- res = ctx @ Wout + bout + query ----------------
__global__ __launch_bounds__(128) void out_gemm(const float* __restrict__ W,
                                                const float* __restrict__ bias,
                                                const float* __restrict__ query) {
    __shared__ float As[2][64 * PITCH_MK];
    __shared__ float Bs[2][32 * PITCH_KN];
    int bm = blockIdx.y * 64, bn = blockIdx.x * 64;
    int tid = threadIdx.x, w = tid >> 5, lane = tid & 31;
    int wm = w >> 1, wn = w & 1, g = lane >> 2, tig = lane & 3;
    float c[2][4][4] = {};
    const float* Abase = g_ctx + (size_t)bm * D_MODEL;
    const float* Wbase = W + bn;
    auto issue = [&](int buf, int k0) {
        #pragma unroll
        for (int it = 0; it < 4; it++) {
            int i = tid + it * 128;
            int r = i >> 3, q = (i & 7) * 4;
            cp16(&As[buf][r * PITCH_MK + q], Abase + (size_t)r * D_MODEL + k0 + q);
        }
        #pragma unroll
        for (int it = 0; it < 4; it++) {
            int i = tid + it * 128;
            int k = i >> 4, q = (i & 15) * 4;
            cp16(&Bs[buf][k * PITCH_KN + q], Wbase + (size_t)(k0 + k) * D_MODEL + q);
        }
    };
    issue(0, 0); CP_COMMIT;
    const int NCH = D_MODEL / 32;
    for (int ci = 0; ci < NCH; ci++) {
        int cur = ci & 1;
        if (ci + 1 < NCH) { issue(cur ^ 1, (ci + 1) * 32); CP_COMMIT; CP_WAIT1; }
        else CP_WAIT0;
        __syncthreads();
        mma_tile_kn(c, (const unsigned*)As[cur], (const unsigned*)Bs[cur], wm, wn, g, tig);
        __syncthreads();
    }
    #pragma unroll
    for (int mt = 0; mt < 2; mt++)
        #pragma unroll
        for (int nt = 0; nt < 4; nt++) {
            int row = bm + wm * 32 + mt * 16 + g;
            int col = bn + wn * 32 + nt * 8 + tig * 2;
            size_t i0 = (size_t)row * D_MODEL + col;
            size_t i2 = (size_t)(row + 8) * D_MODEL + col;
            g_res[i0]     = c[mt][nt][0] + bias[col]     + query[i0];
            g_res[i0 + 1] = c[mt][nt][1] + bias[col + 1] + query[i0 + 1];
            g_res[i2]     = c[mt][nt][2] + bias[col]     + query[i2];
            g_res[i2 + 1] = c[mt][nt][3] + bias[col + 1] + query[i2 + 1];
        }
}

// ---------------- layernorm ----------------
__global__ void ln_kernel(const float* __restrict__ gamma, const float* __restrict__ beta,
                          float* __restrict__ out) {
    __shared__ float shs[8];
    __shared__ float shq[8];
    int row = blockIdx.x;
    const float* x = g_res + (size_t)row * D_MODEL;
    int tid = threadIdx.x;
    float v0 = x[tid], v1 = x[tid + 256];
    float s = v0 + v1, sq = v0 * v0 + v1 * v1;
    #pragma unroll
    for (int o = 16; o > 0; o >>= 1) {
        s  += __shfl_xor_sync(0xffffffffu, s, o);
        sq += __shfl_xor_sync(0xffffffffu, sq, o);
    }
    if ((tid & 31) == 0) { shs[tid >> 5] = s; shq[tid >> 5] = sq; }
    __syncthreads();
    s = 0.f; sq = 0.f;
    #pragma unroll
    for (int w = 0; w < 8; w++) { s += shs[w]; sq += shq[w]; }
    float mu = s * (1.f / D_MODEL);
    float var = sq * (1.f / D_MODEL) - mu * mu;
    float inv = rsqrtf(var + 1e-5f);
    out[(size_t)row * D_MODEL + tid]       = (v0 - mu) * inv * gamma[tid] + beta[tid];
    out[(size_t)row * D_MODEL + tid + 256] = (v1 - mu) * inv * gamma[tid + 256] + beta[tid + 256];
}

// ---------------- launch ----------------
extern "C" void kernel_launch(void* const* d_in, const int* in_sizes, int n_in,
                              void* d_out, int out_size) {
    const float*         query = (const float*)d_in[0];
    const float*         hw    = (const float*)d_in[1];
    const float*         Wqkv  = (const float*)d_in[2];
    const float*         bqkv  = (const float*)d_in[3];
    const float*         Wout  = (const float*)d_in[4];
    const float*         bout  = (const float*)d_in[5];
    const float*         gamma = (const float*)d_in[6];
    const float*         beta  = (const float*)d_in[7];
    const unsigned char* kpm   = (const unsigned char*)d_in[8];
    float* out = (float*)d_out;

    cudaFuncSetAttribute(flash_kernel, cudaFuncAttributeMaxDynamicSharedMemorySize, FLASH_SMEM);

    prep_kernel<<<1, 512>>>(hw);
    qkv_gemm<<<dim3(N3 / 64, M_TOTAL / 64), 128>>>(query, Wqkv, bqkv);
    pack_qk<<<dim3(M_TOTAL / 64, NHEADS), 256>>>();
    pack_v<<<dim3(TSEQ / 64, BATCH, NHEADS * DCHUNKS), 256>>>();
    zero_ctx<<<(M_TOTAL * D_MODEL / 4) / 256, 256>>>();
    flash_kernel<<<dim3(DCHUNKS, TSEQ / 64, NHEADS * BATCH), 128, FLASH_SMEM>>>(kpm);
    out_gemm<<<dim3(D_MODEL / 64, M_TOTAL / 64), 128>>>(Wout, bout, query);
    ln_kernel<<<M_TOTAL, 256>>>(gamma, beta, out);
}

// round 7
// speedup vs baseline: 4.0664x; 1.1014x over previous
#include <cuda_runtime.h>
#include <math.h>
#include <stdint.h>

#define D_MODEL 512
#define NHEADS  8
#define TSEQ    1024
#define BATCH   4
#define M_TOTAL 4096
#define N3      1536
#define KSTR    448
#define DCHUNKS 8
#define RESCH   3        /* resident Q chunks */

#define PITCH    40      /* [mn][k-pair-permuted] smem pitch (words), conflict-free */
#define PITCH_MK 36
#define PITCH_KN 72
#define CHW      (64 * PITCH)
/* 3 resident Q + 2 streaming Q + 2 K + 4 V = 11 chunks = 112640 B -> 2 CTA/SM */
#define FLASH_SMEM (11 * CHW * 4)
#define LOG2E 1.4426950408889634f

// ---------------- scratch ----------------
__device__ float g_qkv[(size_t)M_TOTAL * N3];
__device__ float g_ctx[(size_t)M_TOTAL * D_MODEL];
__device__ float g_res[(size_t)M_TOTAL * D_MODEL];
__device__ float g_qp[(size_t)NHEADS * M_TOTAL * KSTR];
__device__ float g_kp[(size_t)NHEADS * M_TOTAL * KSTR];
__device__ float g_vp[(size_t)NHEADS * DCHUNKS * BATCH * 64 * TSEQ];
__device__ float g_mask[NHEADS][D_MODEL];
__device__ float g_inv_scale[NHEADS];
__device__ int   g_lo[NHEADS];
__device__ int   g_hi[NHEADS];

// ---------------- helpers ----------------
__device__ __forceinline__ unsigned f2tf32(float x) {
    unsigned u; asm("cvt.rna.tf32.f32 %0, %1;\n" : "=r"(u) : "f"(x)); return u;
}
__device__ __forceinline__ float ex2f(float x) {
    float y; asm("ex2.approx.f32 %0, %1;\n" : "=f"(y) : "f"(x)); return y;
}
__device__ __forceinline__ void mma_tf32(float d[4], const unsigned a[4], const unsigned b[2]) {
    asm volatile(
        "mma.sync.aligned.m16n8k8.row.col.f32.tf32.tf32.f32 "
        "{%0,%1,%2,%3}, {%4,%5,%6,%7}, {%8,%9}, {%0,%1,%2,%3};\n"
        : "+f"(d[0]), "+f"(d[1]), "+f"(d[2]), "+f"(d[3])
        : "r"(a[0]), "r"(a[1]), "r"(a[2]), "r"(a[3]), "r"(b[0]), "r"(b[1]));
}
__device__ __forceinline__ void cp16(void* s, const void* gm) {
    unsigned sa = (unsigned)__cvta_generic_to_shared(s);
    asm volatile("cp.async.cg.shared.global [%0], [%1], 16;\n" :: "r"(sa), "l"(gm));
}
#define CP_COMMIT asm volatile("cp.async.commit_group;\n")
#define CP_WAIT0  asm volatile("cp.async.wait_group 0;\n")
#define CP_WAIT1  asm volatile("cp.async.wait_group 1;\n")

// ---------------- prep ----------------
__global__ void prep_kernel(const float* __restrict__ hw) {
    __shared__ float s_start[NHEADS], s_dim[NHEADS];
    int tid = threadIdx.x;
    if (tid == 0) {
        float m = hw[0];
        for (int h = 1; h < NHEADS; h++) m = fmaxf(m, hw[h]);
        float e[NHEADS]; float sum = 0.f;
        for (int h = 0; h < NHEADS; h++) { e[h] = expf(hw[h] - m); sum += e[h]; }
        float start = 0.f;
        for (int h = 0; h < NHEADS; h++) {
            float gate = e[h] / sum;
            float dim = 16.f + gate * (float)(D_MODEL - 16 * NHEADS);
            if (dim < 0.f) dim = 0.f;
            s_start[h] = start; s_dim[h] = dim;
            g_inv_scale[h] = rsqrtf(dim + 1e-6f);
            start += dim;
        }
    }
    __syncthreads();
    if (tid < D_MODEL) {
        float pos = (float)tid;
        for (int h = 0; h < NHEADS; h++) {
            float l = 1.f / (1.f + expf(-(pos - s_start[h]) * 10.f));
            float r = 1.f / (1.f + expf(-(s_start[h] + s_dim[h] - pos) * 10.f));
            g_mask[h][tid] = l * r;
        }
    }
    __syncthreads();
    if (tid == 0) {
        for (int h = 0; h < NHEADS; h++) {
            int lo = D_MODEL, hi = 0;
            for (int d = 0; d < D_MODEL; d++)
                if (g_mask[h][d] > 1e-6f) { if (d < lo) lo = d; hi = d + 1; }
            if (lo >= hi) { lo = 0; hi = 0; }
            g_lo[h] = lo; g_hi[h] = hi;
        }
    }
}

// ---------------- shared GEMM MMA step ----------------
__device__ __forceinline__ void mma_tile_kn(float c[2][4][4], const unsigned* As, const unsigned* Bs,
                                            int wm, int wn, int g, int tig) {
    #pragma unroll
    for (int kq = 0; kq < 32; kq += 8) {
        unsigned a[2][4], b[4][2];
        #pragma unroll
        for (int mt = 0; mt < 2; mt++) {
            int mr = wm * 32 + mt * 16;
            a[mt][0] = As[(mr + g) * PITCH_MK + kq + tig];
            a[mt][1] = As[(mr + g + 8) * PITCH_MK + kq + tig];
            a[mt][2] = As[(mr + g) * PITCH_MK + kq + tig + 4];
            a[mt][3] = As[(mr + g + 8) * PITCH_MK + kq + tig + 4];
        }
        #pragma unroll
        for (int nt = 0; nt < 4; nt++) {
            int nr = wn * 32 + nt * 8;
            b[nt][0] = Bs[(kq + tig) * PITCH_KN + nr + g];
            b[nt][1] = Bs[(kq + tig + 4) * PITCH_KN + nr + g];
        }
        #pragma unroll
        for (int mt = 0; mt < 2; mt++)
            #pragma unroll
            for (int nt = 0; nt < 4; nt++)
                mma_tf32(c[mt][nt], a[mt], b[nt]);
    }
}

// ---------------- qkv = query @ Wqkv + bqkv ----------------
__global__ __launch_bounds__(128) void qkv_gemm(const float* __restrict__ A,
                                                const float* __restrict__ W,
                                                const float* __restrict__ bias) {
    __shared__ float As[2][64 * PITCH_MK];
    __shared__ float Bs[2][32 * PITCH_KN];
    int bm = blockIdx.y * 64, bn = blockIdx.x * 64;
    int tid = threadIdx.x, w = tid >> 5, lane = tid & 31;
    int wm = w >> 1, wn = w & 1, g = lane >> 2, tig = lane & 3;
    float c[2][4][4] = {};
    const float* Abase = A + (size_t)bm * D_MODEL;
    const float* Wbase = W + bn;
    auto issue = [&](int buf, int k0) {
        #pragma unroll
        for (int it = 0; it < 4; it++) {
            int i = tid + it * 128;
            int r = i >> 3, q = (i & 7) * 4;
            cp16(&As[buf][r * PITCH_MK + q], Abase + (size_t)r * D_MODEL + k0 + q);
        }
        #pragma unroll
        for (int it = 0; it < 4; it++) {
            int i = tid + it * 128;
            int k = i >> 4, q = (i & 15) * 4;
            cp16(&Bs[buf][k * PITCH_KN + q], Wbase + (size_t)(k0 + k) * N3 + q);
        }
    };
    issue(0, 0); CP_COMMIT;
    const int NCH = D_MODEL / 32;
    for (int ci = 0; ci < NCH; ci++) {
        int cur = ci & 1;
        if (ci + 1 < NCH) { issue(cur ^ 1, (ci + 1) * 32); CP_COMMIT; CP_WAIT1; }
        else CP_WAIT0;
        __syncthreads();
        mma_tile_kn(c, (const unsigned*)As[cur], (const unsigned*)Bs[cur], wm, wn, g, tig);
        __syncthreads();
    }
    #pragma unroll
    for (int mt = 0; mt < 2; mt++)
        #pragma unroll
        for (int nt = 0; nt < 4; nt++) {
            int row = bm + wm * 32 + mt * 16 + g;
            int col = bn + wn * 32 + nt * 8 + tig * 2;
            g_qkv[(size_t)row * N3 + col]           = c[mt][nt][0] + bias[col];
            g_qkv[(size_t)row * N3 + col + 1]       = c[mt][nt][1] + bias[col + 1];
            g_qkv[(size_t)(row + 8) * N3 + col]     = c[mt][nt][2] + bias[col];
            g_qkv[(size_t)(row + 8) * N3 + col + 1] = c[mt][nt][3] + bias[col + 1];
        }
}

// ---------------- pack Q/K ----------------
__global__ __launch_bounds__(256) void pack_qk() {
    int h = blockIdx.y;
    int row0 = blockIdx.x * 64;
    int klo = g_lo[h] & ~31;
    int khi = (g_hi[h] + 31) & ~31; if (khi > D_MODEL) khi = D_MODEL;
    int per = (khi - klo) >> 2;
    int tid = threadIdx.x;
    const float* mask = g_mask[h];
    float qscale = g_inv_scale[h] * LOG2E;
    #pragma unroll
    for (int which = 0; which < 2; which++) {
        float* dstbase = (which ? g_kp : g_qp) + ((size_t)h * M_TOTAL + row0) * KSTR;
        float sc = which ? 1.f : qscale;
        #pragma unroll
        for (int rb = 0; rb < 2; rb++) {
            int r = rb * 32 + (tid >> 3);
            const float* src = g_qkv + (size_t)(row0 + r) * N3 + which * D_MODEL;
            float* dst = dstbase + (size_t)r * KSTR;
            for (int f = (tid & 7); f < per; f += 8) {
                int k = klo + f * 4;
                float4 v = *(const float4*)(src + k);
                v.x *= mask[k] * sc;     v.y *= mask[k + 1] * sc;
                v.z *= mask[k + 2] * sc; v.w *= mask[k + 3] * sc;
                int kw = f * 4;
                int gb = kw & ~7;
                int off = (kw & 4) ? 1 : 0;
                dst[gb + off]     = __uint_as_float(f2tf32(v.x));
                dst[gb + off + 2] = __uint_as_float(f2tf32(v.y));
                dst[gb + off + 4] = __uint_as_float(f2tf32(v.z));
                dst[gb + off + 6] = __uint_as_float(f2tf32(v.w));
            }
        }
    }
}

// ---------------- pack V ----------------
__global__ __launch_bounds__(256) void pack_v() {
    int z = blockIdx.z, h = z >> 3, dc = z & 7;
    int b = blockIdx.y;
    int s0 = blockIdx.x * 64;
    int d0 = dc * 64;
    if (g_hi[h] <= d0 || g_lo[h] >= d0 + 64) return;
    __shared__ float tile[64][65];
    int tid = threadIdx.x;
    const float* mask = g_mask[h];
    const float* vsrc = g_qkv + (size_t)(b * TSEQ + s0) * N3 + 2 * D_MODEL + d0;
    for (int i = tid; i < 64 * 16; i += 256) {
        int s = i >> 4, dseg = (i & 15) * 4;
        float4 v = *(const float4*)(vsrc + (size_t)s * N3 + dseg);
        tile[dseg][s]     = v.x * mask[d0 + dseg];
        tile[dseg + 1][s] = v.y * mask[d0 + dseg + 1];
        tile[dseg + 2][s] = v.z * mask[d0 + dseg + 2];
        tile[dseg + 3][s] = v.w * mask[d0 + dseg + 3];
    }
    __syncthreads();
    float* dst = g_vp + ((size_t)z * BATCH + b) * 64 * TSEQ;
    for (int i = tid; i < 64 * 64; i += 256) {
        int d = i >> 6, sl = i & 63;
        int sp = (sl & ~7) + 2 * (sl & 3) + ((sl >> 2) & 1);
        dst[(size_t)d * TSEQ + s0 + sp] = __uint_as_float(f2tf32(tile[d][sl]));
    }
}

// ---------------- zero ctx ----------------
__global__ void zero_ctx() {
    size_t i = (size_t)blockIdx.x * blockDim.x + threadIdx.x;
    ((float4*)g_ctx)[i] = make_float4(0.f, 0.f, 0.f, 0.f);
}

// ---------------- flash: S once per d-chunk PAIR, PV into both chunks ----------------
__global__ __launch_bounds__(128) void flash_kernel(const unsigned char* __restrict__ kpm) {
    extern __shared__ unsigned sm[];
    unsigned* SQR = sm;                                // 3 resident Q chunks
    unsigned* SQS = sm + RESCH * CHW;                  // 2 streaming Q chunks
    unsigned* SKb[2] = { sm + (RESCH + 2) * CHW, sm + (RESCH + 3) * CHW };
    unsigned* SV   = sm + (RESCH + 4) * CHW;           // 4 bufs: (nd*2+half)*CHW
    int z = blockIdx.z, h = z >> 2, b = z & 3;
    int t0 = blockIdx.y * 64;
    int dclo = g_lo[h] >> 6, dchi = (g_hi[h] - 1) >> 6;   // inclusive active chunk range
    int dc0 = dclo + 2 * blockIdx.x;
    if (dc0 > dchi) return;
    int nd2 = (dc0 + 1 <= dchi) ? 2 : 1;
    int klo = g_lo[h] & ~31;
    int khi = (g_hi[h] + 31) & ~31; if (khi > D_MODEL) khi = D_MODEL;
    int nch = (khi - klo) >> 5;
    const float* qp  = g_qp + ((size_t)h * M_TOTAL + b * TSEQ + t0) * KSTR;
    const float* kp  = g_kp + ((size_t)h * M_TOTAL + b * TSEQ) * KSTR;
    const float* vp0 = g_vp + ((size_t)(h * 8 + dc0) * BATCH + b) * 64 * TSEQ;
    const float* vp1 = g_vp + ((size_t)(h * 8 + dc0 + 1) * BATCH + b) * 64 * TSEQ;
    const unsigned char* kpb = kpm + b * TSEQ;
    int tid = threadIdx.x, w = tid >> 5, lane = tid & 31, g = lane >> 2, tig = lane & 3;
    int mr = w * 16;

    // resident Q
    int nres = nch < RESCH ? nch : RESCH;
    for (int ci = 0; ci < nres; ci++)
        #pragma unroll
        for (int it = 0; it < 4; it++) {
            int i = tid + it * 128;
            int r = i >> 3, seg = (i & 7) * 4;
            cp16(&SQR[ci * CHW + r * PITCH + seg], qp + (size_t)r * KSTR + ci * 32 + seg);
        }
    CP_COMMIT;

    float o0[8][4] = {}, o1[8][4] = {};
    float m0 = -1e30f, m1 = -1e30f, l0 = 0.f, l1 = 0.f;

    for (int s0 = 0; s0 < TSEQ; s0 += 64) {
        // V prefetch: both halves for 1-2 chunks
        #pragma unroll
        for (int half = 0; half < 2; half++)
            #pragma unroll
            for (int it = 0; it < 4; it++) {
                int i = tid + it * 128;
                int r = i >> 3, seg = (i & 7) * 4;
                cp16(&SV[half * CHW + r * PITCH + seg], vp0 + (size_t)r * TSEQ + s0 + half * 32 + seg);
            }
        if (nd2 == 2)
            #pragma unroll
            for (int half = 0; half < 2; half++)
                #pragma unroll
                for (int it = 0; it < 4; it++) {
                    int i = tid + it * 128;
                    int r = i >> 3, seg = (i & 7) * 4;
                    cp16(&SV[(2 + half) * CHW + r * PITCH + seg], vp1 + (size_t)r * TSEQ + s0 + half * 32 + seg);
                }
        CP_COMMIT;

        auto issue_chunk = [&](int buf, int ci) {
            #pragma unroll
            for (int it = 0; it < 4; it++) {
                int i = tid + it * 128;
                int r = i >> 3, seg = (i & 7) * 4;
                cp16(&SKb[buf][r * PITCH + seg], kp + (size_t)(s0 + r) * KSTR + ci * 32 + seg);
            }
            if (ci >= RESCH)
                #pragma unroll
                for (int it = 0; it < 4; it++) {
                    int i = tid + it * 128;
                    int r = i >> 3, seg = (i & 7) * 4;
                    cp16(&SQS[buf * CHW + r * PITCH + seg], qp + (size_t)r * KSTR + ci * 32 + seg);
                }
        };
        issue_chunk(0, 0); CP_COMMIT;

        // ---- S (log2-scaled) ----
        float c[8][4] = {};
        for (int ci = 0; ci < nch; ci++) {
            int cur = ci & 1;
            if (ci + 1 < nch) { issue_chunk(cur ^ 1, ci + 1); CP_COMMIT; CP_WAIT1; }
            else CP_WAIT0;
            __syncthreads();
            const unsigned* SQ = (ci < RESCH) ? (SQR + ci * CHW) : (SQS + cur * CHW);
            const unsigned* SK = SKb[cur];
            #pragma unroll
            for (int kq = 0; kq < 32; kq += 8) {
                uint2 aA = *(const uint2*)&SQ[(mr + g) * PITCH + kq + 2 * tig];
                uint2 aB = *(const uint2*)&SQ[(mr + g + 8) * PITCH + kq + 2 * tig];
                unsigned a[4] = {aA.x, aB.x, aA.y, aB.y};
                #pragma unroll
                for (int nt = 0; nt < 8; nt++) {
                    uint2 bb = *(const uint2*)&SK[(nt * 8 + g) * PITCH + kq + 2 * tig];
                    unsigned bf[2] = {bb.x, bb.y};
                    mma_tf32(c[nt], a, bf);
                }
            }
            __syncthreads();
        }
        // ---- key-padding ----
        #pragma unroll
        for (int nt = 0; nt < 8; nt++) {
            int col = s0 + nt * 8 + tig * 2;
            if (kpb[col])     { c[nt][0] = -1e9f; c[nt][2] = -1e9f; }
            if (kpb[col + 1]) { c[nt][1] = -1e9f; c[nt][3] = -1e9f; }
        }
        // ---- running max + rescale ----
        float mx0 = -1e30f, mx1 = -1e30f;
        #pragma unroll
        for (int nt = 0; nt < 8; nt++) {
            mx0 = fmaxf(mx0, fmaxf(c[nt][0], c[nt][1]));
            mx1 = fmaxf(mx1, fmaxf(c[nt][2], c[nt][3]));
        }
        mx0 = fmaxf(mx0, __shfl_xor_sync(0xffffffffu, mx0, 1));
        mx0 = fmaxf(mx0, __shfl_xor_sync(0xffffffffu, mx0, 2));
        mx1 = fmaxf(mx1, __shfl_xor_sync(0xffffffffu, mx1, 1));
        mx1 = fmaxf(mx1, __shfl_xor_sync(0xffffffffu, mx1, 2));
        float nm0 = fmaxf(m0, mx0), nm1 = fmaxf(m1, mx1);
        float al0 = ex2f(m0 - nm0), al1 = ex2f(m1 - nm1);
        m0 = nm0; m1 = nm1;
        if (al0 != 1.f || al1 != 1.f) {
            l0 *= al0; l1 *= al1;
            #pragma unroll
            for (int nt = 0; nt < 8; nt++) {
                o0[nt][0] *= al0; o0[nt][1] *= al0; o0[nt][2] *= al1; o0[nt][3] *= al1;
                o1[nt][0] *= al0; o1[nt][1] *= al0; o1[nt][2] *= al1; o1[nt][3] *= al1;
            }
        }
        // ---- exp + PV for both chunks (P shared; a-frag reused) ----
        unsigned* SP = SKb[0];
        int p0 = (tig < 2) ? 4 * tig : 4 * (tig - 2) + 1;
        float rs0 = 0.f, rs1 = 0.f;
        #pragma unroll
        for (int half = 0; half < 2; half++) {
            #pragma unroll
            for (int nt = 0; nt < 4; nt++) {
                int src = half * 4 + nt;
                float e0 = ex2f(c[src][0] - m0), e1 = ex2f(c[src][1] - m0);
                float e2 = ex2f(c[src][2] - m1), e3 = ex2f(c[src][3] - m1);
                rs0 += e0 + e1; rs1 += e2 + e3;
                SP[(mr + g) * PITCH + nt * 8 + p0]         = f2tf32(e0);
                SP[(mr + g) * PITCH + nt * 8 + p0 + 2]     = f2tf32(e1);
                SP[(mr + g + 8) * PITCH + nt * 8 + p0]     = f2tf32(e2);
                SP[(mr + g + 8) * PITCH + nt * 8 + p0 + 2] = f2tf32(e3);
            }
            __syncwarp();
            const unsigned* V0 = SV + half * CHW;
            const unsigned* V1 = SV + (2 + half) * CHW;
            #pragma unroll
            for (int kq = 0; kq < 32; kq += 8) {
                uint2 aA = *(const uint2*)&SP[(mr + g) * PITCH + kq + 2 * tig];
                uint2 aB = *(const uint2*)&SP[(mr + g + 8) * PITCH + kq + 2 * tig];
                unsigned a[4] = {aA.x, aB.x, aA.y, aB.y};
                #pragma unroll
                for (int nt = 0; nt < 8; nt++) {
                    uint2 bb = *(const uint2*)&V0[(nt * 8 + g) * PITCH + kq + 2 * tig];
                    unsigned bf[2] = {bb.x, bb.y};
                    mma_tf32(o0[nt], a, bf);
                }
                if (nd2 == 2) {
                    #pragma unroll
                    for (int nt = 0; nt < 8; nt++) {
                        uint2 bb = *(const uint2*)&V1[(nt * 8 + g) * PITCH + kq + 2 * tig];
                        unsigned bf[2] = {bb.x, bb.y};
                        mma_tf32(o1[nt], a, bf);
                    }
                }
            }
            __syncwarp();
        }
        rs0 += __shfl_xor_sync(0xffffffffu, rs0, 1);
        rs0 += __shfl_xor_sync(0xffffffffu, rs0, 2);
        rs1 += __shfl_xor_sync(0xffffffffu, rs1, 1);
        rs1 += __shfl_xor_sync(0xffffffffu, rs1, 2);
        l0 += rs0; l1 += rs1;
        __syncthreads();
    }
    // ---- epilogue ----
    float inv0 = 1.f / l0, inv1 = 1.f / l1;
    size_t rowbase = (size_t)(b * TSEQ + t0 + mr + g) * D_MODEL;
    #pragma unroll
    for (int nt = 0; nt < 8; nt++) {
        int col = dc0 * 64 + nt * 8 + tig * 2;
        size_t r0 = rowbase + col;
        size_t r1 = r0 + (size_t)8 * D_MODEL;
        atomicAdd(&g_ctx[r0],     o0[nt][0] * inv0);
        atomicAdd(&g_ctx[r0 + 1], o0[nt][1] * inv0);
        atomicAdd(&g_ctx[r1],     o0[nt][2] * inv1);
        atomicAdd(&g_ctx[r1 + 1], o0[nt][3] * inv1);
    }
    if (nd2 == 2) {
        #pragma unroll
        for (int nt = 0; nt < 8; nt++) {
            int col = dc0 * 64 + 64 + nt * 8 + tig * 2;
            size_t r0 = rowbase + col;
            size_t r1 = r0 + (size_t)8 * D_MODEL;
            atomicAdd(&g_ctx[r0],     o1[nt][0] * inv0);
            atomicAdd(&g_ctx[r0 + 1], o1[nt][1] * inv0);
            atomicAdd(&g_ctx[r1],     o1[nt][2] * inv1);
            atomicAdd(&g_ctx[r1 + 1], o1[nt][3] * inv1);
        }
    }
}

// ---------------- res = ctx @ Wout + bout + query ----------------
__global__ __launch_bounds__(128) void out_gemm(const float* __restrict__ W,
                                                const float* __restrict__ bias,
                                                const float* __restrict__ query) {
    __shared__ float As[2][64 * PITCH_MK];
    __shared__ float Bs[2][32 * PITCH_KN];
    int bm = blockIdx.y * 64, bn = blockIdx.x * 64;
    int tid = threadIdx.x, w = tid >> 5, lane = tid & 31;
    int wm = w >> 1, wn = w & 1, g = lane >> 2, tig = lane & 3;
    float c[2][4][4] = {};
    const float* Abase = g_ctx + (size_t)bm * D_MODEL;
    const float* Wbase = W + bn;
    auto issue = [&](int buf, int k0) {
        #pragma unroll
        for (int it = 0; it < 4; it++) {
            int i = tid + it * 128;
            int r = i >> 3, q = (i & 7) * 4;
            cp16(&As[buf][r * PITCH_MK + q], Abase + (size_t)r * D_MODEL + k0 + q);
        }
        #pragma unroll
        for (int it = 0; it < 4; it++) {
            int i = tid + it * 128;
            int k = i >> 4, q = (i & 15) * 4;
            cp16(&Bs[buf][k * PITCH_KN + q], Wbase + (size_t)(k0 + k) * D_MODEL + q);
        }
    };
    issue(0, 0); CP_COMMIT;
    const int NCH = D_MODEL / 32;
    for (int ci = 0; ci < NCH; ci++) {
        int cur = ci & 1;
        if (ci + 1 < NCH) { issue(cur ^ 1, (ci + 1) * 32); CP_COMMIT; CP_WAIT1; }
        else CP_WAIT0;
        __syncthreads();
        mma_tile_kn(c, (const unsigned*)As[cur], (const unsigned*)Bs[cur], wm, wn, g, tig);
        __syncthreads();
    }
    #pragma unroll
    for (int mt = 0; mt < 2; mt++)
        #pragma unroll
        for (int nt = 0; nt < 4; nt++) {
            int row = bm + wm * 32 + mt * 16 + g;
            int col = bn + wn * 32 + nt * 8 + tig * 2;
            size_t i0 = (size_t)row * D_MODEL + col;
            size_t i2 = (size_t)(row + 8) * D_MODEL + col;
            g_res[i0]     = c[mt][nt][0] + bias[col]     + query[i0];
            g_res[i0 + 1] = c[mt][nt][1] + bias[col + 1] + query[i0 + 1];
            g_res[i2]     = c[mt][nt][2] + bias[col]     + query[i2];
            g_res[i2 + 1] = c[mt][nt][3] + bias[col + 1] + query[i2 + 1];
        }
}

// ---------------- layernorm ----------------
__global__ void ln_kernel(const float* __restrict__ gamma, const float* __restrict__ beta,
                          float* __restrict__ out) {
    __shared__ float shs[8];
    __shared__ float shq[8];
    int row = blockIdx.x;
    const float* x = g_res + (size_t)row * D_MODEL;
    int tid = threadIdx.x;
    float v0 = x[tid], v1 = x[tid + 256];
    float s = v0 + v1, sq = v0 * v0 + v1 * v1;
    #pragma unroll
    for (int o = 16; o > 0; o >>= 1) {
        s  += __shfl_xor_sync(0xffffffffu, s, o);
        sq += __shfl_xor_sync(0xffffffffu, sq, o);
    }
    if ((tid & 31) == 0) { shs[tid >> 5] = s; shq[tid >> 5] = sq; }
    __syncthreads();
    s = 0.f; sq = 0.f;
    #pragma unroll
    for (int w = 0; w < 8; w++) { s += shs[w]; sq += shq[w]; }
    float mu = s * (1.f / D_MODEL);
    float var = sq * (1.f / D_MODEL) - mu * mu;
    float inv = rsqrtf(var + 1e-5f);
    out[(size_t)row * D_MODEL + tid]       = (v0 - mu) * inv * gamma[tid] + beta[tid];
    out[(size_t)row * D_MODEL + tid + 256] = (v1 - mu) * inv * gamma[tid + 256] + beta[tid + 256];
}

// ---------------- launch ----------------
extern "C" void kernel_launch(void* const* d_in, const int* in_sizes, int n_in,
                              void* d_out, int out_size) {
    const float*         query = (const float*)d_in[0];
    const float*         hw    = (const float*)d_in[1];
    const float*         Wqkv  = (const float*)d_in[2];
    const float*         bqkv  = (const float*)d_in[3];
    const float*         Wout  = (const float*)d_in[4];
    const float*         bout  = (const float*)d_in[5];
    const float*         gamma = (const float*)d_in[6];
    const float*         beta  = (const float*)d_in[7];
    const unsigned char* kpm   = (const unsigned char*)d_in[8];
    float* out = (float*)d_out;

    cudaFuncSetAttribute(flash_kernel, cudaFuncAttributeMaxDynamicSharedMemorySize, FLASH_SMEM);

    prep_kernel<<<1, 512>>>(hw);
    qkv_gemm<<<dim3(N3 / 64, M_TOTAL / 64), 128>>>(query, Wqkv, bqkv);
    pack_qk<<<dim3(M_TOTAL / 64, NHEADS), 256>>>();
    pack_v<<<dim3(TSEQ / 64, BATCH, NHEADS * DCHUNKS), 256>>>();
    zero_ctx<<<(M_TOTAL * D_MODEL / 4) / 256, 256>>>();
    flash_kernel<<<dim3(4, TSEQ / 64, NHEADS * BATCH), 128, FLASH_SMEM>>>(kpm);
    out_gemm<<<dim3(D_MODEL / 64, M_TOTAL / 64), 128>>>(Wout, bout, query);
    ln_kernel<<<M_TOTAL, 256>>>(gamma, beta, out);
}